// round 3
// baseline (speedup 1.0000x reference)
#include <cuda_runtime.h>
#include <math.h>

// Problem constants: B=4, N=1024, C=512, H=8, HD=64, SCALE=0.125
// qkv raw layout: [4096 rows = b*1024+seq][2048 cols = which*512 + h*64 + d]

__device__ float g_qkv1[4096 * 2048];
__device__ float g_qkv2[4096 * 2048];
__device__ float g_pre[4 * 4096 * 512];
__device__ float g_part_orth[16384];
__device__ float g_part_lc[4096];

struct AttnArgs {
    const float* q[4];
    const float* k[4];
    const float* v[4];
    float*       o[4];
};

// ---------------------------------------------------------------------------
// SGEMM NT: C[m][n] = sum_k A[m][k]*B[n][k] (+ bias[n])
// A: MxK row-major, B: NxK row-major, C: MxN row-major.
// 128x128 block tile, BK=16, 8x8 per thread, 256 threads.
// All dims divisible by tiles for this problem (M=4096, N in {512,2048}, K=512).
// ---------------------------------------------------------------------------
__global__ void __launch_bounds__(256) sgemm_nt(
    const float* __restrict__ A, const float* __restrict__ B,
    const float* __restrict__ bias, float* __restrict__ C,
    int M, int Nn, int K)
{
    __shared__ float As[16][128];
    __shared__ float Bs[16][128];
    const int tid = threadIdx.x;
    const int tx = tid & 15, ty = tid >> 4;
    const float* Ab = A + (size_t)(blockIdx.y * 128) * K;
    const float* Bb = B + (size_t)(blockIdx.x * 128) * K;

    float acc[8][8];
#pragma unroll
    for (int i = 0; i < 8; i++)
#pragma unroll
        for (int j = 0; j < 8; j++) acc[i][j] = 0.f;

    for (int k0 = 0; k0 < K; k0 += 16) {
#pragma unroll
        for (int l = 0; l < 2; l++) {
            int f = tid + l * 256;          // [0,512)
            int row = f >> 2;               // [0,128)
            int c4 = (f & 3) << 2;          // {0,4,8,12}
            float4 av = *(const float4*)(Ab + (size_t)row * K + k0 + c4);
            As[c4 + 0][row] = av.x; As[c4 + 1][row] = av.y;
            As[c4 + 2][row] = av.z; As[c4 + 3][row] = av.w;
            float4 bv = *(const float4*)(Bb + (size_t)row * K + k0 + c4);
            Bs[c4 + 0][row] = bv.x; Bs[c4 + 1][row] = bv.y;
            Bs[c4 + 2][row] = bv.z; Bs[c4 + 3][row] = bv.w;
        }
        __syncthreads();
#pragma unroll
        for (int kk = 0; kk < 16; kk++) {
            float af[8], bf[8];
#pragma unroll
            for (int i = 0; i < 8; i++) af[i] = As[kk][ty * 8 + i];
#pragma unroll
            for (int j = 0; j < 8; j++) bf[j] = Bs[kk][tx * 8 + j];
#pragma unroll
            for (int i = 0; i < 8; i++)
#pragma unroll
                for (int j = 0; j < 8; j++) acc[i][j] += af[i] * bf[j];
        }
        __syncthreads();
    }

    float bv[8];
#pragma unroll
    for (int j = 0; j < 8; j++)
        bv[j] = bias ? bias[blockIdx.x * 128 + tx * 8 + j] : 0.f;

#pragma unroll
    for (int i = 0; i < 8; i++) {
        int m = blockIdx.y * 128 + ty * 8 + i;
        int n0 = blockIdx.x * 128 + tx * 8;
        float4 r0, r1;
        r0.x = acc[i][0] + bv[0]; r0.y = acc[i][1] + bv[1];
        r0.z = acc[i][2] + bv[2]; r0.w = acc[i][3] + bv[3];
        r1.x = acc[i][4] + bv[4]; r1.y = acc[i][5] + bv[5];
        r1.z = acc[i][6] + bv[6]; r1.w = acc[i][7] + bv[7];
        *(float4*)(C + (size_t)m * Nn + n0)     = r0;
        *(float4*)(C + (size_t)m * Nn + n0 + 4) = r1;
    }
}

// ---------------------------------------------------------------------------
// Flash attention, fp32. Block: 64 query rows, iterate 32 tiles of 32 keys.
// q/k/v rows live in qkv raw buffer with row stride 2048 floats.
// Output: [4096][512] with col = h*64+d (row stride 512).
// ---------------------------------------------------------------------------
__global__ void __launch_bounds__(256) attn_kernel(AttnArgs P)
{
    const int z = blockIdx.z;          // which attention
    const int bh = blockIdx.y;         // b*8+h
    const int qt = blockIdx.x;         // query tile [0,16)
    const int b = bh >> 3, h = bh & 7;
    const float* qg = P.q[z] + (size_t)b * 1024 * 2048 + h * 64;
    const float* kg = P.k[z] + (size_t)b * 1024 * 2048 + h * 64;
    const float* vg = P.v[z] + (size_t)b * 1024 * 2048 + h * 64;
    float*       og = P.o[z] + (size_t)b * 1024 * 512 + h * 64;

    __shared__ float qs[64][65];
    __shared__ float ks[32][65];
    __shared__ float vs[32][64];
    __shared__ float Ss[64][33];
    __shared__ float red[64][16];
    __shared__ float mrow[64], lrow[64], arow[64];

    const int tid = threadIdx.x;
    const int tx = tid & 15, ty = tid >> 4;

    // load q tile (64 rows x 64 floats)
    for (int f = tid; f < 64 * 16; f += 256) {
        int r = f >> 4, c = (f & 15) << 2;
        float4 qv = *(const float4*)(qg + (size_t)(qt * 64 + r) * 2048 + c);
        qs[r][c] = qv.x; qs[r][c + 1] = qv.y; qs[r][c + 2] = qv.z; qs[r][c + 3] = qv.w;
    }
    if (tid < 64) { mrow[tid] = -1e30f; lrow[tid] = 0.f; }

    float acc[4][4];
#pragma unroll
    for (int i = 0; i < 4; i++)
#pragma unroll
        for (int j = 0; j < 4; j++) acc[i][j] = 0.f;

    for (int t = 0; t < 32; t++) {
        __syncthreads();  // prior iteration finished reading ks/vs/Ss
        for (int f = tid; f < 32 * 16; f += 256) {
            int r = f >> 4, c = (f & 15) << 2;
            float4 kv = *(const float4*)(kg + (size_t)(t * 32 + r) * 2048 + c);
            ks[r][c] = kv.x; ks[r][c + 1] = kv.y; ks[r][c + 2] = kv.z; ks[r][c + 3] = kv.w;
            float4 vv = *(const float4*)(vg + (size_t)(t * 32 + r) * 2048 + c);
            vs[r][c] = vv.x; vs[r][c + 1] = vv.y; vs[r][c + 2] = vv.z; vs[r][c + 3] = vv.w;
        }
        __syncthreads();

        // S tile: rows ty*4..+3, cols tx*2..+1
        float s0[4] = {0.f, 0.f, 0.f, 0.f};
        float s1[4] = {0.f, 0.f, 0.f, 0.f};
        const int j0 = tx * 2, j1 = tx * 2 + 1;
#pragma unroll 8
        for (int kk = 0; kk < 64; kk++) {
            float kv0 = ks[j0][kk], kv1 = ks[j1][kk];
#pragma unroll
            for (int i = 0; i < 4; i++) {
                float qv = qs[ty * 4 + i][kk];
                s0[i] += qv * kv0;
                s1[i] += qv * kv1;
            }
        }
#pragma unroll
        for (int i = 0; i < 4; i++) {
            s0[i] *= 0.125f; s1[i] *= 0.125f;
            red[ty * 4 + i][tx] = fmaxf(s0[i], s1[i]);
        }
        __syncthreads();

        if (tid < 64) {
            float mo = mrow[tid], mn = mo;
#pragma unroll
            for (int xx = 0; xx < 16; xx++) mn = fmaxf(mn, red[tid][xx]);
            mrow[tid] = mn;
            arow[tid] = expf(mo - mn);   // first iter: expf(-inf-ish) = 0
        }
        __syncthreads();

#pragma unroll
        for (int i = 0; i < 4; i++) {
            int r = ty * 4 + i;
            float mn = mrow[r];
            float p0 = expf(s0[i] - mn);
            float p1 = expf(s1[i] - mn);
            Ss[r][j0] = p0; Ss[r][j1] = p1;
            red[r][tx] = p0 + p1;
            float a = arow[r];
#pragma unroll
            for (int d = 0; d < 4; d++) acc[i][d] *= a;
        }
        __syncthreads();

        if (tid < 64) {
            float s = 0.f;
#pragma unroll
            for (int xx = 0; xx < 16; xx++) s += red[tid][xx];
            lrow[tid] = lrow[tid] * arow[tid] + s;
        }

        // o += P @ V : rows ty*4..+3, d cols tx*4..+3
#pragma unroll
        for (int j = 0; j < 32; j++) {
            float4 vv = *(const float4*)&vs[j][tx * 4];
#pragma unroll
            for (int i = 0; i < 4; i++) {
                float p = Ss[ty * 4 + i][j];
                acc[i][0] += p * vv.x; acc[i][1] += p * vv.y;
                acc[i][2] += p * vv.z; acc[i][3] += p * vv.w;
            }
        }
    }
    __syncthreads();

#pragma unroll
    for (int i = 0; i < 4; i++) {
        int r = ty * 4 + i;
        float inv = 1.f / lrow[r];
        float4 o4;
        o4.x = acc[i][0] * inv; o4.y = acc[i][1] * inv;
        o4.z = acc[i][2] * inv; o4.w = acc[i][3] * inv;
        *(float4*)(og + (size_t)(qt * 64 + r) * 512 + tx * 4) = o4;
    }
}

// ---------------------------------------------------------------------------
// Ortho loss tiles: for (b,h), G = qn @ qtn^T; accumulate sum of off-diag G^2.
// Normalization folded into epilogue via per-row inverse norms (HD=64 per row).
// z in [0,32): loss x on qkv1; z in [32,64): loss y on qkv2.
// ---------------------------------------------------------------------------
__global__ void __launch_bounds__(256) ortho_kernel(
    const float* __restrict__ qkv1, const float* __restrict__ qkv2,
    float* __restrict__ part)
{
    const int z = blockIdx.z;
    const int bh = z & 31;
    const int b = bh >> 3, h = bh & 7;
    const float* base = (z < 32) ? qkv1 : qkv2;
    const float* qa = base + (size_t)b * 1024 * 2048 + h * 64;        // q  (which=0)
    const float* qb = qa + 1536;                                      // qt (which=3)
    const int i0 = blockIdx.y * 64, j0 = blockIdx.x * 64;

    __shared__ float As[64][65];
    __shared__ float Bs[64][65];
    __shared__ float inva[64], invb[64];
    __shared__ float rbuf[256];

    const int tid = threadIdx.x;
    const int tx = tid & 15, ty = tid >> 4;

    for (int f = tid; f < 64 * 16; f += 256) {
        int r = f >> 4, c = (f & 15) << 2;
        float4 a4 = *(const float4*)(qa + (size_t)(i0 + r) * 2048 + c);
        As[r][c] = a4.x; As[r][c + 1] = a4.y; As[r][c + 2] = a4.z; As[r][c + 3] = a4.w;
        float4 b4 = *(const float4*)(qb + (size_t)(j0 + r) * 2048 + c);
        Bs[r][c] = b4.x; Bs[r][c + 1] = b4.y; Bs[r][c + 2] = b4.z; Bs[r][c + 3] = b4.w;
    }
    __syncthreads();

    if (tid < 64) {
        float s = 0.f;
#pragma unroll 8
        for (int c = 0; c < 64; c++) { float v = As[tid][c]; s += v * v; }
        inva[tid] = 1.f / fmaxf(sqrtf(s), 1e-12f);
    } else if (tid < 128) {
        int r = tid - 64;
        float s = 0.f;
#pragma unroll 8
        for (int c = 0; c < 64; c++) { float v = Bs[r][c]; s += v * v; }
        invb[r] = 1.f / fmaxf(sqrtf(s), 1e-12f);
    }
    __syncthreads();

    float dacc[4][4];
#pragma unroll
    for (int i = 0; i < 4; i++)
#pragma unroll
        for (int j = 0; j < 4; j++) dacc[i][j] = 0.f;

#pragma unroll 8
    for (int kk = 0; kk < 64; kk++) {
        float a[4], bb[4];
#pragma unroll
        for (int i = 0; i < 4; i++) a[i] = As[ty * 4 + i][kk];
#pragma unroll
        for (int j = 0; j < 4; j++) bb[j] = Bs[tx * 4 + j][kk];
#pragma unroll
        for (int i = 0; i < 4; i++)
#pragma unroll
            for (int j = 0; j < 4; j++) dacc[i][j] += a[i] * bb[j];
    }

    float ssum = 0.f;
#pragma unroll
    for (int i = 0; i < 4; i++)
#pragma unroll
        for (int j = 0; j < 4; j++) {
            float g = dacc[i][j] * inva[ty * 4 + i] * invb[tx * 4 + j];
            if (i0 + ty * 4 + i != j0 + tx * 4 + j) ssum += g * g;
        }

    rbuf[tid] = ssum;
    __syncthreads();
    for (int st = 128; st > 0; st >>= 1) {
        if (tid < st) rbuf[tid] += rbuf[tid + st];
        __syncthreads();
    }
    if (tid == 0) part[z * 256 + blockIdx.y * 16 + blockIdx.x] = rbuf[0];
}

// ---------------------------------------------------------------------------
// lc partials: per row r of xc/yc (post-projection), 1 - cos(xc_n, yc_n)
// ---------------------------------------------------------------------------
__global__ void __launch_bounds__(128) lc_kernel(
    const float* __restrict__ xc, const float* __restrict__ yc,
    float* __restrict__ part)
{
    const int r = blockIdx.x;
    const float* xr = xc + (size_t)r * 512;
    const float* yr = yc + (size_t)r * 512;
    __shared__ float sxx[128], syy[128], sxy[128];
    const int tid = threadIdx.x;
    float xx = 0.f, yy = 0.f, xy = 0.f;
    for (int i = tid; i < 512; i += 128) {
        float xv = xr[i], yv = yr[i];
        xx += xv * xv; yy += yv * yv; xy += xv * yv;
    }
    sxx[tid] = xx; syy[tid] = yy; sxy[tid] = xy;
    __syncthreads();
    for (int st = 64; st > 0; st >>= 1) {
        if (tid < st) {
            sxx[tid] += sxx[tid + st];
            syy[tid] += syy[tid + st];
            sxy[tid] += sxy[tid + st];
        }
        __syncthreads();
    }
    if (tid == 0) {
        float nx = fmaxf(sqrtf(sxx[0]), 1e-12f);
        float ny = fmaxf(sqrtf(syy[0]), 1e-12f);
        part[r] = 1.f - sxy[0] / (nx * ny);
    }
}

// ---------------------------------------------------------------------------
// Deterministic final reductions for the 3 scalars
// ---------------------------------------------------------------------------
__global__ void __launch_bounds__(256) finalize_kernel(
    const float* __restrict__ porth, const float* __restrict__ plc,
    float* __restrict__ outs)
{
    __shared__ float sh[256];
    const int tid = threadIdx.x;

    float s = 0.f;
    for (int i = tid; i < 8192; i += 256) s += porth[i];
    sh[tid] = s; __syncthreads();
    for (int st = 128; st > 0; st >>= 1) { if (tid < st) sh[tid] += sh[tid + st]; __syncthreads(); }
    if (tid == 0) outs[0] = sh[0] * (1.f / 4194304.f);
    __syncthreads();

    s = 0.f;
    for (int i = tid; i < 8192; i += 256) s += porth[8192 + i];
    sh[tid] = s; __syncthreads();
    for (int st = 128; st > 0; st >>= 1) { if (tid < st) sh[tid] += sh[tid + st]; __syncthreads(); }
    if (tid == 0) outs[1] = sh[0] * (1.f / 4194304.f);
    __syncthreads();

    s = 0.f;
    for (int i = tid; i < 4096; i += 256) s += plc[i];
    sh[tid] = s; __syncthreads();
    for (int st = 128; st > 0; st >>= 1) { if (tid < st) sh[tid] += sh[tid + st]; __syncthreads(); }
    if (tid == 0) outs[2] = sh[0] * (1.f / 4096.f);
}

// ---------------------------------------------------------------------------
extern "C" void kernel_launch(void* const* d_in, const int* in_sizes, int n_in,
                              void* d_out, int out_size)
{
    (void)in_sizes; (void)n_in;
    const float* x   = (const float*)d_in[0];
    const float* y   = (const float*)d_in[1];
    const float* Wq1 = (const float*)d_in[2];
    const float* Wq2 = (const float*)d_in[3];
    const float* W[4]  = {(const float*)d_in[4], (const float*)d_in[6],
                          (const float*)d_in[8], (const float*)d_in[10]};
    const float* bb[4] = {(const float*)d_in[5], (const float*)d_in[7],
                          (const float*)d_in[9], (const float*)d_in[11]};
    float* out = (float*)d_out;

    float *qkv1, *qkv2, *pre, *porth, *plc;
    cudaGetSymbolAddress((void**)&qkv1, g_qkv1);
    cudaGetSymbolAddress((void**)&qkv2, g_qkv2);
    cudaGetSymbolAddress((void**)&pre, g_pre);
    cudaGetSymbolAddress((void**)&porth, g_part_orth);
    cudaGetSymbolAddress((void**)&plc, g_part_lc);

    const int chunk = (out_size - 3) / 4;  // 2097152 = 4096*512

    // QKV projections
    sgemm_nt<<<dim3(16, 32), 256>>>(x, Wq1, nullptr, qkv1, 4096, 2048, 512);
    sgemm_nt<<<dim3(16, 32), 256>>>(y, Wq2, nullptr, qkv2, 4096, 2048, 512);

    // Ortho losses (both, 32 heads each)
    ortho_kernel<<<dim3(16, 16, 64), 256>>>(qkv1, qkv2, porth);

    // 4 attentions:
    //   pre[0] = attn(qy, kx, vx)  -> xc
    //   pre[1] = attn(qx, ky, vy)  -> yc
    //   pre[2] = attn(qtx, kx, vx) -> xt
    //   pre[3] = attn(qty, ky, vy) -> yt
    AttnArgs aa;
    aa.q[0] = qkv2;        aa.k[0] = qkv1 + 512; aa.v[0] = qkv1 + 1024; aa.o[0] = pre;
    aa.q[1] = qkv1;        aa.k[1] = qkv2 + 512; aa.v[1] = qkv2 + 1024; aa.o[1] = pre + 2097152;
    aa.q[2] = qkv1 + 1536; aa.k[2] = qkv1 + 512; aa.v[2] = qkv1 + 1024; aa.o[2] = pre + 2 * 2097152;
    aa.q[3] = qkv2 + 1536; aa.k[3] = qkv2 + 512; aa.v[3] = qkv2 + 1024; aa.o[3] = pre + 3 * 2097152;
    attn_kernel<<<dim3(16, 32, 4), 256>>>(aa);

    // Output projections straight into d_out (order: xc, yc, xt, yt)
    for (int i = 0; i < 4; i++)
        sgemm_nt<<<dim3(4, 32), 256>>>(pre + (size_t)i * 2097152, W[i], bb[i],
                                       out + (size_t)i * chunk, 4096, 512, 512);

    // lc on post-projection xc, yc
    lc_kernel<<<4096, 128>>>(out, out + chunk, plc);

    // scalars: lorthx, lorthy, lc
    finalize_kernel<<<1, 256>>>(porth, plc, out + (size_t)out_size - 3);
}

// round 5
// speedup vs baseline: 1.4299x; 1.4299x over previous
#include <cuda_runtime.h>
#include <cuda_bf16.h>
#include <math.h>
#include <stdint.h>

// Problem constants: B=4, N=1024, C=512, H=8, HD=64, SCALE=0.125
// qkv raw layout: [4096 rows = b*1024+seq][2048 cols = which*512 + h*64 + d]

__device__ float g_qkv1[4096 * 2048];
__device__ float g_qkv2[4096 * 2048];
__device__ float g_pre[4 * 4096 * 512];
__device__ float g_part_orth[16384];
__device__ float g_part_lc[4096];

// ===========================================================================
// mma.sync (base-target HMMA) machinery: bf16 hi/lo split, fp32 accumulate
// ===========================================================================
__device__ __forceinline__ uint32_t smem_u32(const void* p) {
    uint32_t a;
    asm("{ .reg .u64 t; cvta.to.shared.u64 t, %1; cvt.u32.u64 %0, t; }"
        : "=r"(a) : "l"(p));
    return a;
}

__device__ __forceinline__ void ldsm4(uint32_t* r, uint32_t addr) {
    asm volatile("ldmatrix.sync.aligned.m8n8.x4.shared.b16 {%0,%1,%2,%3}, [%4];"
                 : "=r"(r[0]), "=r"(r[1]), "=r"(r[2]), "=r"(r[3]) : "r"(addr));
}

__device__ __forceinline__ void mma16816(float* c, const uint32_t* a,
                                         uint32_t b0, uint32_t b1) {
    asm volatile(
        "mma.sync.aligned.m16n8k16.row.col.f32.bf16.bf16.f32 "
        "{%0,%1,%2,%3}, {%4,%5,%6,%7}, {%8,%9}, {%0,%1,%2,%3};"
        : "+f"(c[0]), "+f"(c[1]), "+f"(c[2]), "+f"(c[3])
        : "r"(a[0]), "r"(a[1]), "r"(a[2]), "r"(a[3]), "r"(b0), "r"(b1));
}

// SMEM tile geometry: 128 rows x 32 bf16 cols, row stride 40 elems (80 bytes).
// 80B stride => for 8 consecutive rows the 16B chunks fall at
// 0,80,32,112,64,16,96,48 mod 128 -> conflict-free ldmatrix phases.
#define T_STRIDE_B 80
#define T_BYTES    10240             // 128 * 80
#define BUF_BYTES  40960             // Ah,Al,Bh,Bl
#define GEMM_SMEM  (2 * BUF_BYTES)   // double buffered
#define ORTHO_SMEM (GEMM_SMEM + 2048)

// Load 128x32 fp32 tile into regs (4 float4 per thread, 256 threads).
__device__ __forceinline__ void gload(float4* r, const float* __restrict__ g,
                                      int ld, int tid, int koff) {
#pragma unroll
    for (int l = 0; l < 4; l++) {
        int idx = tid + l * 256;
        int row = idx >> 3, c4 = (idx & 7) << 2;
        r[l] = *(const float4*)(g + (size_t)row * ld + koff + c4);
    }
}

// Split to bf16 hi/lo and store into smem tile (hi at base, lo at base+T_BYTES).
__device__ __forceinline__ void cstore(const float4* r, char* base, int tid) {
#pragma unroll
    for (int l = 0; l < 4; l++) {
        int idx = tid + l * 256;
        int row = idx >> 3, c4 = (idx & 7) << 2;
        float4 v = r[l];
        __nv_bfloat162 h0 = __floats2bfloat162_rn(v.x, v.y);
        __nv_bfloat162 h1 = __floats2bfloat162_rn(v.z, v.w);
        __nv_bfloat162 l0 = __floats2bfloat162_rn(v.x - __bfloat162float(h0.x),
                                                  v.y - __bfloat162float(h0.y));
        __nv_bfloat162 l1 = __floats2bfloat162_rn(v.z - __bfloat162float(h1.x),
                                                  v.w - __bfloat162float(h1.y));
        int off = row * T_STRIDE_B + (c4 << 1);
        uint2 hv, lv;
        hv.x = *(uint32_t*)&h0; hv.y = *(uint32_t*)&h1;
        lv.x = *(uint32_t*)&l0; lv.y = *(uint32_t*)&l1;
        *(uint2*)(base + off) = hv;
        *(uint2*)(base + T_BYTES + off) = lv;
    }
}

// One BK=32 chunk of MMA work: 2 k16-steps x 16 tiles x 3 split terms.
// sbuf: shared byte address of buffer (Ah at +0, Al +T_BYTES, Bh +2T, Bl +3T).
__device__ __forceinline__ void compute_chunk(float acc[4][4][4], uint32_t sbuf,
                                              int lane, int warp_m, int warp_n) {
    const uint32_t aBase = sbuf;
    const uint32_t bBase = sbuf + 2 * T_BYTES;
#pragma unroll
    for (int kk = 0; kk < 2; kk++) {
        uint32_t Ah[4][4], Al[4][4], Bh[2][4], Bl[2][4];
#pragma unroll
        for (int mt = 0; mt < 4; mt++) {
            int row = warp_m * 64 + mt * 16 + (lane & 15);
            uint32_t addr = aBase + row * T_STRIDE_B + kk * 32 + ((lane >> 4) << 4);
            ldsm4(Ah[mt], addr);
            ldsm4(Al[mt], addr + T_BYTES);
        }
#pragma unroll
        for (int nt2 = 0; nt2 < 2; nt2++) {
            int q = lane >> 3;
            int rown = warp_n * 32 + nt2 * 16 + ((q >> 1) << 3) + (lane & 7);
            uint32_t addr = bBase + rown * T_STRIDE_B + kk * 32 + ((q & 1) << 4);
            ldsm4(Bh[nt2], addr);
            ldsm4(Bl[nt2], addr + T_BYTES);
        }
#pragma unroll
        for (int mt = 0; mt < 4; mt++)
#pragma unroll
            for (int nt = 0; nt < 4; nt++) {
                uint32_t bh0 = Bh[nt >> 1][(nt & 1) * 2];
                uint32_t bh1 = Bh[nt >> 1][(nt & 1) * 2 + 1];
                uint32_t bl0 = Bl[nt >> 1][(nt & 1) * 2];
                uint32_t bl1 = Bl[nt >> 1][(nt & 1) * 2 + 1];
                mma16816(acc[mt][nt], Ah[mt], bh0, bh1);
                mma16816(acc[mt][nt], Ah[mt], bl0, bl1);
                mma16816(acc[mt][nt], Al[mt], bh0, bh1);
            }
    }
}

// ===========================================================================
// HMMA GEMM NT: C[M,N] = A[MxK] * B[NxK]^T (+bias), fp32 in/out.
// grid: (Nn/128, M/128), 256 threads, double-buffered smem.
// ===========================================================================
__global__ void __launch_bounds__(256) hm_gemm_nt(
    const float* __restrict__ A, const float* __restrict__ B,
    const float* __restrict__ bias, float* __restrict__ C, int K, int Nn)
{
    extern __shared__ char sm[];
    const uint32_t sb = smem_u32(sm);
    const int tid = threadIdx.x, lane = tid & 31, wid = tid >> 5;
    const int warp_m = wid >> 2, warp_n = wid & 3;

    const float* Ab = A + (size_t)(blockIdx.y * 128) * K;
    const float* Bb = B + (size_t)(blockIdx.x * 128) * K;

    float acc[4][4][4];
#pragma unroll
    for (int i = 0; i < 4; i++)
#pragma unroll
        for (int j = 0; j < 4; j++)
#pragma unroll
            for (int e = 0; e < 4; e++) acc[i][j][e] = 0.f;

    const int nch = K >> 5;
    float4 ar[4], br[4];
    gload(ar, Ab, K, tid, 0);
    gload(br, Bb, K, tid, 0);
    cstore(ar, sm, tid);
    cstore(br, sm + 2 * T_BYTES, tid);
    __syncthreads();

    int s = 0;
    for (int ch = 0; ch < nch; ch++) {
        const bool pre = (ch + 1 < nch);
        if (pre) {
            gload(ar, Ab, K, tid, (ch + 1) * 32);
            gload(br, Bb, K, tid, (ch + 1) * 32);
        }
        compute_chunk(acc, sb + s * BUF_BYTES, lane, warp_m, warp_n);
        if (pre) {
            char* nb = sm + (s ^ 1) * BUF_BYTES;
            cstore(ar, nb, tid);
            cstore(br, nb + 2 * T_BYTES, tid);
        }
        __syncthreads();
        s ^= 1;
    }

    // epilogue
#pragma unroll
    for (int mt = 0; mt < 4; mt++)
#pragma unroll
        for (int nt = 0; nt < 4; nt++) {
            int row = blockIdx.y * 128 + warp_m * 64 + mt * 16 + (lane >> 2);
            int col = blockIdx.x * 128 + warp_n * 32 + nt * 8 + ((lane & 3) << 1);
            float b0 = 0.f, b1 = 0.f;
            if (bias) { b0 = bias[col]; b1 = bias[col + 1]; }
            float2 v0, v1;
            v0.x = acc[mt][nt][0] + b0; v0.y = acc[mt][nt][1] + b1;
            v1.x = acc[mt][nt][2] + b0; v1.y = acc[mt][nt][3] + b1;
            *(float2*)(C + (size_t)row * Nn + col) = v0;
            *(float2*)(C + (size_t)(row + 8) * Nn + col) = v1;
        }
}

// ===========================================================================
// HMMA ortho loss: per (loss, b, h), 128x128 tile of G = q @ qt^T (K=64),
// epilogue normalizes by row/col norms and reduces off-diagonal sum sq.
// grid: (8, 8, 64), 256 threads.
// ===========================================================================
__global__ void __launch_bounds__(256) hm_ortho(
    const float* __restrict__ qkv1, const float* __restrict__ qkv2,
    float* __restrict__ part)
{
    extern __shared__ char sm[];
    const uint32_t sb = smem_u32(sm);
    float* inva = (float*)(sm + GEMM_SMEM);
    float* invb = (float*)(sm + GEMM_SMEM + 512);

    const int tid = threadIdx.x, lane = tid & 31, wid = tid >> 5;
    const int warp_m = wid >> 2, warp_n = wid & 3;

    const int z = blockIdx.z;
    const int bh = z & 31;
    const int b = bh >> 3, h = bh & 7;
    const float* base = (z < 32) ? qkv1 : qkv2;
    const float* qa = base + (size_t)b * 1024 * 2048 + h * 64;  // q  (which=0)
    const float* qb = qa + 1536;                                 // qt (which=3)
    const int i0 = blockIdx.y * 128, j0 = blockIdx.x * 128;
    const float* Ab = qa + (size_t)i0 * 2048;
    const float* Bb = qb + (size_t)j0 * 2048;

    float acc[4][4][4];
#pragma unroll
    for (int i = 0; i < 4; i++)
#pragma unroll
        for (int j = 0; j < 4; j++)
#pragma unroll
            for (int e = 0; e < 4; e++) acc[i][j][e] = 0.f;

    float4 ar[4], br[4];
    gload(ar, Ab, 2048, tid, 0);
    gload(br, Bb, 2048, tid, 0);
    cstore(ar, sm, tid);
    cstore(br, sm + 2 * T_BYTES, tid);

    // row norms (gmem reads, overlapped with smem stores above)
    {
        const float* rp = (tid < 128) ? (Ab + (size_t)tid * 2048)
                                      : (Bb + (size_t)(tid - 128) * 2048);
        float ssq = 0.f;
#pragma unroll
        for (int c = 0; c < 64; c += 4) {
            float4 v = *(const float4*)(rp + c);
            ssq += v.x * v.x + v.y * v.y + v.z * v.z + v.w * v.w;
        }
        float inv = 1.f / fmaxf(sqrtf(ssq), 1e-12f);
        if (tid < 128) inva[tid] = inv;
        else           invb[tid - 128] = inv;
    }
    __syncthreads();

    // chunk 0 compute + prefetch chunk 1
    gload(ar, Ab, 2048, tid, 32);
    gload(br, Bb, 2048, tid, 32);
    compute_chunk(acc, sb, lane, warp_m, warp_n);
    cstore(ar, sm + BUF_BYTES, tid);
    cstore(br, sm + BUF_BYTES + 2 * T_BYTES, tid);
    __syncthreads();
    compute_chunk(acc, sb + BUF_BYTES, lane, warp_m, warp_n);

    // epilogue: normalize, square, off-diagonal reduce
    float ssum = 0.f;
#pragma unroll
    for (int mt = 0; mt < 4; mt++)
#pragma unroll
        for (int nt = 0; nt < 4; nt++) {
            int r = warp_m * 64 + mt * 16 + (lane >> 2);
            int c = warp_n * 32 + nt * 8 + ((lane & 3) << 1);
            int gi0 = i0 + r, gi1 = gi0 + 8;
            int gj0 = j0 + c, gj1 = gj0 + 1;
            float ia0 = inva[r], ia1 = inva[r + 8];
            float ib0 = invb[c], ib1 = invb[c + 1];
            float g00 = acc[mt][nt][0] * ia0 * ib0;
            float g01 = acc[mt][nt][1] * ia0 * ib1;
            float g10 = acc[mt][nt][2] * ia1 * ib0;
            float g11 = acc[mt][nt][3] * ia1 * ib1;
            if (gi0 != gj0) ssum += g00 * g00;
            if (gi0 != gj1) ssum += g01 * g01;
            if (gi1 != gj0) ssum += g10 * g10;
            if (gi1 != gj1) ssum += g11 * g11;
        }

    __syncthreads();
    float* rb = (float*)sm;
    rb[tid] = ssum;
    __syncthreads();
    for (int st = 128; st > 0; st >>= 1) {
        if (tid < st) rb[tid] += rb[tid + st];
        __syncthreads();
    }
    if (tid == 0)
        part[(size_t)z * 64 + blockIdx.y * 8 + blockIdx.x] = rb[0];
}

// ===========================================================================
// Flash attention, fp32 (validated in round 2; __expf).
// ===========================================================================
struct AttnArgs {
    const float* q[4];
    const float* k[4];
    const float* v[4];
    float*       o[4];
};

__global__ void __launch_bounds__(256) attn_kernel(AttnArgs P)
{
    const int z = blockIdx.z;
    const int bh = blockIdx.y;
    const int qt = blockIdx.x;
    const int b = bh >> 3, h = bh & 7;
    const float* qg = P.q[z] + (size_t)b * 1024 * 2048 + h * 64;
    const float* kg = P.k[z] + (size_t)b * 1024 * 2048 + h * 64;
    const float* vg = P.v[z] + (size_t)b * 1024 * 2048 + h * 64;
    float*       og = P.o[z] + (size_t)b * 1024 * 512 + h * 64;

    __shared__ float qs[64][65];
    __shared__ float ks[32][65];
    __shared__ float vs[32][64];
    __shared__ float Ss[64][33];
    __shared__ float red[64][16];
    __shared__ float mrow[64], lrow[64], arow[64];

    const int tid = threadIdx.x;
    const int tx = tid & 15, ty = tid >> 4;

    for (int f = tid; f < 64 * 16; f += 256) {
        int r = f >> 4, c = (f & 15) << 2;
        float4 qv = *(const float4*)(qg + (size_t)(qt * 64 + r) * 2048 + c);
        qs[r][c] = qv.x; qs[r][c + 1] = qv.y; qs[r][c + 2] = qv.z; qs[r][c + 3] = qv.w;
    }
    if (tid < 64) { mrow[tid] = -1e30f; lrow[tid] = 0.f; }

    float acc[4][4];
#pragma unroll
    for (int i = 0; i < 4; i++)
#pragma unroll
        for (int j = 0; j < 4; j++) acc[i][j] = 0.f;

    for (int t = 0; t < 32; t++) {
        __syncthreads();
        for (int f = tid; f < 32 * 16; f += 256) {
            int r = f >> 4, c = (f & 15) << 2;
            float4 kv = *(const float4*)(kg + (size_t)(t * 32 + r) * 2048 + c);
            ks[r][c] = kv.x; ks[r][c + 1] = kv.y; ks[r][c + 2] = kv.z; ks[r][c + 3] = kv.w;
            float4 vv = *(const float4*)(vg + (size_t)(t * 32 + r) * 2048 + c);
            vs[r][c] = vv.x; vs[r][c + 1] = vv.y; vs[r][c + 2] = vv.z; vs[r][c + 3] = vv.w;
        }
        __syncthreads();

        float s0[4] = {0.f, 0.f, 0.f, 0.f};
        float s1[4] = {0.f, 0.f, 0.f, 0.f};
        const int j0 = tx * 2, j1 = tx * 2 + 1;
#pragma unroll 8
        for (int kk = 0; kk < 64; kk++) {
            float kv0 = ks[j0][kk], kv1 = ks[j1][kk];
#pragma unroll
            for (int i = 0; i < 4; i++) {
                float qv = qs[ty * 4 + i][kk];
                s0[i] += qv * kv0;
                s1[i] += qv * kv1;
            }
        }
#pragma unroll
        for (int i = 0; i < 4; i++) {
            s0[i] *= 0.125f; s1[i] *= 0.125f;
            red[ty * 4 + i][tx] = fmaxf(s0[i], s1[i]);
        }
        __syncthreads();

        if (tid < 64) {
            float mo = mrow[tid], mn = mo;
#pragma unroll
            for (int xx = 0; xx < 16; xx++) mn = fmaxf(mn, red[tid][xx]);
            mrow[tid] = mn;
            arow[tid] = __expf(mo - mn);
        }
        __syncthreads();

#pragma unroll
        for (int i = 0; i < 4; i++) {
            int r = ty * 4 + i;
            float mn = mrow[r];
            float p0 = __expf(s0[i] - mn);
            float p1 = __expf(s1[i] - mn);
            Ss[r][j0] = p0; Ss[r][j1] = p1;
            red[r][tx] = p0 + p1;
            float a = arow[r];
#pragma unroll
            for (int d = 0; d < 4; d++) acc[i][d] *= a;
        }
        __syncthreads();

        if (tid < 64) {
            float s = 0.f;
#pragma unroll
            for (int xx = 0; xx < 16; xx++) s += red[tid][xx];
            lrow[tid] = lrow[tid] * arow[tid] + s;
        }

#pragma unroll
        for (int j = 0; j < 32; j++) {
            float4 vv = *(const float4*)&vs[j][tx * 4];
#pragma unroll
            for (int i = 0; i < 4; i++) {
                float p = Ss[ty * 4 + i][j];
                acc[i][0] += p * vv.x; acc[i][1] += p * vv.y;
                acc[i][2] += p * vv.z; acc[i][3] += p * vv.w;
            }
        }
    }
    __syncthreads();

#pragma unroll
    for (int i = 0; i < 4; i++) {
        int r = ty * 4 + i;
        float inv = 1.f / lrow[r];
        float4 o4;
        o4.x = acc[i][0] * inv; o4.y = acc[i][1] * inv;
        o4.z = acc[i][2] * inv; o4.w = acc[i][3] * inv;
        *(float4*)(og + (size_t)(qt * 64 + r) * 512 + tx * 4) = o4;
    }
}

// ---------------------------------------------------------------------------
// lc partials: per row r of xc/yc (post-projection), 1 - cos(xc_n, yc_n)
// ---------------------------------------------------------------------------
__global__ void __launch_bounds__(128) lc_kernel(
    const float* __restrict__ xc, const float* __restrict__ yc,
    float* __restrict__ part)
{
    const int r = blockIdx.x;
    const float* xr = xc + (size_t)r * 512;
    const float* yr = yc + (size_t)r * 512;
    __shared__ float sxx[128], syy[128], sxy[128];
    const int tid = threadIdx.x;
    float xx = 0.f, yy = 0.f, xy = 0.f;
    for (int i = tid; i < 512; i += 128) {
        float xv = xr[i], yv = yr[i];
        xx += xv * xv; yy += yv * yv; xy += xv * yv;
    }
    sxx[tid] = xx; syy[tid] = yy; sxy[tid] = xy;
    __syncthreads();
    for (int st = 64; st > 0; st >>= 1) {
        if (tid < st) {
            sxx[tid] += sxx[tid + st];
            syy[tid] += syy[tid + st];
            sxy[tid] += sxy[tid + st];
        }
        __syncthreads();
    }
    if (tid == 0) {
        float nx = fmaxf(sqrtf(sxx[0]), 1e-12f);
        float ny = fmaxf(sqrtf(syy[0]), 1e-12f);
        part[r] = 1.f - sxy[0] / (nx * ny);
    }
}

// ---------------------------------------------------------------------------
// Deterministic final reductions for the 3 scalars
// ---------------------------------------------------------------------------
__global__ void __launch_bounds__(256) finalize_kernel(
    const float* __restrict__ porth, const float* __restrict__ plc,
    float* __restrict__ outs)
{
    __shared__ float sh[256];
    const int tid = threadIdx.x;

    float s = 0.f;
    for (int i = tid; i < 2048; i += 256) s += porth[i];
    sh[tid] = s; __syncthreads();
    for (int st = 128; st > 0; st >>= 1) { if (tid < st) sh[tid] += sh[tid + st]; __syncthreads(); }
    if (tid == 0) outs[0] = sh[0] * (1.f / 4194304.f);
    __syncthreads();

    s = 0.f;
    for (int i = tid; i < 2048; i += 256) s += porth[2048 + i];
    sh[tid] = s; __syncthreads();
    for (int st = 128; st > 0; st >>= 1) { if (tid < st) sh[tid] += sh[tid + st]; __syncthreads(); }
    if (tid == 0) outs[1] = sh[0] * (1.f / 4194304.f);
    __syncthreads();

    s = 0.f;
    for (int i = tid; i < 4096; i += 256) s += plc[i];
    sh[tid] = s; __syncthreads();
    for (int st = 128; st > 0; st >>= 1) { if (tid < st) sh[tid] += sh[tid + st]; __syncthreads(); }
    if (tid == 0) outs[2] = sh[0] * (1.f / 4096.f);
}

// ---------------------------------------------------------------------------
extern "C" void kernel_launch(void* const* d_in, const int* in_sizes, int n_in,
                              void* d_out, int out_size)
{
    (void)in_sizes; (void)n_in;
    const float* x   = (const float*)d_in[0];
    const float* y   = (const float*)d_in[1];
    const float* Wq1 = (const float*)d_in[2];
    const float* Wq2 = (const float*)d_in[3];
    const float* W[4]  = {(const float*)d_in[4], (const float*)d_in[6],
                          (const float*)d_in[8], (const float*)d_in[10]};
    const float* bb[4] = {(const float*)d_in[5], (const float*)d_in[7],
                          (const float*)d_in[9], (const float*)d_in[11]};
    float* out = (float*)d_out;

    float *qkv1, *qkv2, *pre, *porth, *plc;
    cudaGetSymbolAddress((void**)&qkv1, g_qkv1);
    cudaGetSymbolAddress((void**)&qkv2, g_qkv2);
    cudaGetSymbolAddress((void**)&pre, g_pre);
    cudaGetSymbolAddress((void**)&porth, g_part_orth);
    cudaGetSymbolAddress((void**)&plc, g_part_lc);

    cudaFuncSetAttribute(hm_gemm_nt, cudaFuncAttributeMaxDynamicSharedMemorySize,
                         GEMM_SMEM);
    cudaFuncSetAttribute(hm_ortho, cudaFuncAttributeMaxDynamicSharedMemorySize,
                         ORTHO_SMEM);

    const int chunk = (out_size - 3) / 4;  // 2097152 = 4096*512

    // QKV projections (HMMA bf16-split)
    hm_gemm_nt<<<dim3(16, 32), 256, GEMM_SMEM>>>(x, Wq1, nullptr, qkv1, 512, 2048);
    hm_gemm_nt<<<dim3(16, 32), 256, GEMM_SMEM>>>(y, Wq2, nullptr, qkv2, 512, 2048);

    // Ortho losses (HMMA; both losses, 32 heads each; 128x128 tiles)
    hm_ortho<<<dim3(8, 8, 64), 256, ORTHO_SMEM>>>(qkv1, qkv2, porth);

    // 4 attentions (fp32 flash):
    //   pre[0] = attn(qy, kx, vx)  -> xc
    //   pre[1] = attn(qx, ky, vy)  -> yc
    //   pre[2] = attn(qtx, kx, vx) -> xt
    //   pre[3] = attn(qty, ky, vy) -> yt
    AttnArgs aa;
    aa.q[0] = qkv2;        aa.k[0] = qkv1 + 512; aa.v[0] = qkv1 + 1024; aa.o[0] = pre;
    aa.q[1] = qkv1;        aa.k[1] = qkv2 + 512; aa.v[1] = qkv2 + 1024; aa.o[1] = pre + 2097152;
    aa.q[2] = qkv1 + 1536; aa.k[2] = qkv1 + 512; aa.v[2] = qkv1 + 1024; aa.o[2] = pre + 2 * 2097152;
    aa.q[3] = qkv2 + 1536; aa.k[3] = qkv2 + 512; aa.v[3] = qkv2 + 1024; aa.o[3] = pre + 3 * 2097152;
    attn_kernel<<<dim3(16, 32, 4), 256>>>(aa);

    // Output projections straight into d_out (order: xc, yc, xt, yt)
    for (int i = 0; i < 4; i++)
        hm_gemm_nt<<<dim3(4, 32), 256, GEMM_SMEM>>>(
            pre + (size_t)i * 2097152, W[i], bb[i], out + (size_t)i * chunk, 512, 512);

    // lc on post-projection xc, yc
    lc_kernel<<<4096, 128>>>(out, out + chunk, plc);

    // scalars: lorthx, lorthy, lc
    finalize_kernel<<<1, 256>>>(porth, plc, out + (size_t)out_size - 3);
}

// round 6
// speedup vs baseline: 3.2235x; 2.2544x over previous
#include <cuda_runtime.h>
#include <cuda_bf16.h>
#include <math.h>
#include <stdint.h>

// Problem constants: B=4, N=1024, C=512, H=8, HD=64, SCALE=0.125
// qkv bf16 hi/lo layout: [4096 rows = b*1024+seq][2048 cols = which*512 + h*64 + d]

__device__ __nv_bfloat16 g_q1h[4096 * 2048];
__device__ __nv_bfloat16 g_q1l[4096 * 2048];
__device__ __nv_bfloat16 g_q2h[4096 * 2048];
__device__ __nv_bfloat16 g_q2l[4096 * 2048];
__device__ float g_pre[4 * 4096 * 512];
__device__ float g_part_orth[16384];
__device__ float g_part_lc[4096];

// ===========================================================================
// mma.sync machinery (base-target HMMA): bf16 hi/lo split, fp32 accumulate
// ===========================================================================
__device__ __forceinline__ uint32_t smem_u32(const void* p) {
    uint32_t a;
    asm("{ .reg .u64 t; cvta.to.shared.u64 t, %1; cvt.u32.u64 %0, t; }"
        : "=r"(a) : "l"(p));
    return a;
}
__device__ __forceinline__ void ldsm4(uint32_t* r, uint32_t addr) {
    asm volatile("ldmatrix.sync.aligned.m8n8.x4.shared.b16 {%0,%1,%2,%3}, [%4];"
                 : "=r"(r[0]), "=r"(r[1]), "=r"(r[2]), "=r"(r[3]) : "r"(addr));
}
__device__ __forceinline__ void ldsm4t(uint32_t* r, uint32_t addr) {
    asm volatile("ldmatrix.sync.aligned.m8n8.x4.trans.shared.b16 {%0,%1,%2,%3}, [%4];"
                 : "=r"(r[0]), "=r"(r[1]), "=r"(r[2]), "=r"(r[3]) : "r"(addr));
}
__device__ __forceinline__ void mma16816(float* c, const uint32_t* a,
                                         uint32_t b0, uint32_t b1) {
    asm volatile(
        "mma.sync.aligned.m16n8k16.row.col.f32.bf16.bf16.f32 "
        "{%0,%1,%2,%3}, {%4,%5,%6,%7}, {%8,%9}, {%0,%1,%2,%3};"
        : "+f"(c[0]), "+f"(c[1]), "+f"(c[2]), "+f"(c[3])
        : "r"(a[0]), "r"(a[1]), "r"(a[2]), "r"(a[3]), "r"(b0), "r"(b1));
}
__device__ __forceinline__ uint32_t packbf(float a, float b) {
    __nv_bfloat162 h = __floats2bfloat162_rn(a, b);
    return *(uint32_t*)&h;
}

// ---------------------------------------------------------------------------
// fp32-input GEMM machinery (80B-stride tiles, used by out-projections)
// ---------------------------------------------------------------------------
#define T_STRIDE_B 80
#define T_BYTES    10240
#define BUF_BYTES  40960
#define GEMM_SMEM  (2 * BUF_BYTES)

__device__ __forceinline__ void gload(float4* r, const float* __restrict__ g,
                                      int ld, int tid, int koff) {
#pragma unroll
    for (int l = 0; l < 4; l++) {
        int idx = tid + l * 256;
        int row = idx >> 3, c4 = (idx & 7) << 2;
        r[l] = *(const float4*)(g + (size_t)row * ld + koff + c4);
    }
}
__device__ __forceinline__ void cstore(const float4* r, char* base, int tid) {
#pragma unroll
    for (int l = 0; l < 4; l++) {
        int idx = tid + l * 256;
        int row = idx >> 3, c4 = (idx & 7) << 2;
        float4 v = r[l];
        __nv_bfloat162 h0 = __floats2bfloat162_rn(v.x, v.y);
        __nv_bfloat162 h1 = __floats2bfloat162_rn(v.z, v.w);
        __nv_bfloat162 l0 = __floats2bfloat162_rn(v.x - __bfloat162float(h0.x),
                                                  v.y - __bfloat162float(h0.y));
        __nv_bfloat162 l1 = __floats2bfloat162_rn(v.z - __bfloat162float(h1.x),
                                                  v.w - __bfloat162float(h1.y));
        int off = row * T_STRIDE_B + (c4 << 1);
        uint2 hv, lv;
        hv.x = *(uint32_t*)&h0; hv.y = *(uint32_t*)&h1;
        lv.x = *(uint32_t*)&l0; lv.y = *(uint32_t*)&l1;
        *(uint2*)(base + off) = hv;
        *(uint2*)(base + T_BYTES + off) = lv;
    }
}
__device__ __forceinline__ void compute_chunk(float acc[4][4][4], uint32_t sbuf,
                                              int lane, int warp_m, int warp_n) {
    const uint32_t aBase = sbuf;
    const uint32_t bBase = sbuf + 2 * T_BYTES;
#pragma unroll
    for (int kk = 0; kk < 2; kk++) {
        uint32_t Ah[4][4], Al[4][4], Bh[2][4], Bl[2][4];
#pragma unroll
        for (int mt = 0; mt < 4; mt++) {
            int row = warp_m * 64 + mt * 16 + (lane & 15);
            uint32_t addr = aBase + row * T_STRIDE_B + kk * 32 + ((lane >> 4) << 4);
            ldsm4(Ah[mt], addr);
            ldsm4(Al[mt], addr + T_BYTES);
        }
#pragma unroll
        for (int nt2 = 0; nt2 < 2; nt2++) {
            int q = lane >> 3;
            int rown = warp_n * 32 + nt2 * 16 + ((q >> 1) << 3) + (lane & 7);
            uint32_t addr = bBase + rown * T_STRIDE_B + kk * 32 + ((q & 1) << 4);
            ldsm4(Bh[nt2], addr);
            ldsm4(Bl[nt2], addr + T_BYTES);
        }
#pragma unroll
        for (int mt = 0; mt < 4; mt++)
#pragma unroll
            for (int nt = 0; nt < 4; nt++) {
                uint32_t bh0 = Bh[nt >> 1][(nt & 1) * 2];
                uint32_t bh1 = Bh[nt >> 1][(nt & 1) * 2 + 1];
                uint32_t bl0 = Bl[nt >> 1][(nt & 1) * 2];
                uint32_t bl1 = Bl[nt >> 1][(nt & 1) * 2 + 1];
                mma16816(acc[mt][nt], Ah[mt], bh0, bh1);
                mma16816(acc[mt][nt], Ah[mt], bl0, bl1);
                mma16816(acc[mt][nt], Al[mt], bh0, bh1);
            }
    }
}

// Shared mainloop for fp32-input GEMMs: fills acc for a 128x128 tile.
__device__ __forceinline__ void gemm_mainloop(
    float acc[4][4][4], const float* Ab, const float* Bb, int K,
    char* sm, uint32_t sb, int tid, int lane, int warp_m, int warp_n)
{
    const int nch = K >> 5;
    float4 ar[4], br[4];
    gload(ar, Ab, K, tid, 0);
    gload(br, Bb, K, tid, 0);
    cstore(ar, sm, tid);
    cstore(br, sm + 2 * T_BYTES, tid);
    __syncthreads();
    int s = 0;
    for (int ch = 0; ch < nch; ch++) {
        const bool pre = (ch + 1 < nch);
        if (pre) {
            gload(ar, Ab, K, tid, (ch + 1) * 32);
            gload(br, Bb, K, tid, (ch + 1) * 32);
        }
        compute_chunk(acc, sb + s * BUF_BYTES, lane, warp_m, warp_n);
        if (pre) {
            char* nb = sm + (s ^ 1) * BUF_BYTES;
            cstore(ar, nb, tid);
            cstore(br, nb + 2 * T_BYTES, tid);
        }
        __syncthreads();
        s ^= 1;
    }
}

// ===========================================================================
// QKV projection: fp32 in, bf16 hi/lo out. grid (16, 32), 256 thr.
// ===========================================================================
__global__ void __launch_bounds__(256) hm_gemm_qkv(
    const float* __restrict__ A, const float* __restrict__ B,
    __nv_bfloat16* __restrict__ Oh, __nv_bfloat16* __restrict__ Ol)
{
    extern __shared__ char sm[];
    const uint32_t sb = smem_u32(sm);
    const int tid = threadIdx.x, lane = tid & 31, wid = tid >> 5;
    const int warp_m = wid >> 2, warp_n = wid & 3;
    const int K = 512, Nn = 2048;

    const float* Ab = A + (size_t)(blockIdx.y * 128) * K;
    const float* Bb = B + (size_t)(blockIdx.x * 128) * K;

    float acc[4][4][4];
#pragma unroll
    for (int i = 0; i < 4; i++)
#pragma unroll
        for (int j = 0; j < 4; j++)
#pragma unroll
            for (int e = 0; e < 4; e++) acc[i][j][e] = 0.f;

    gemm_mainloop(acc, Ab, Bb, K, sm, sb, tid, lane, warp_m, warp_n);

#pragma unroll
    for (int mt = 0; mt < 4; mt++)
#pragma unroll
        for (int nt = 0; nt < 4; nt++) {
            int row = blockIdx.y * 128 + warp_m * 64 + mt * 16 + (lane >> 2);
            int col = blockIdx.x * 128 + warp_n * 32 + nt * 8 + ((lane & 3) << 1);
#pragma unroll
            for (int half = 0; half < 2; half++) {
                float v0 = acc[mt][nt][half * 2], v1 = acc[mt][nt][half * 2 + 1];
                int r = row + half * 8;
                __nv_bfloat162 h = __floats2bfloat162_rn(v0, v1);
                __nv_bfloat162 l = __floats2bfloat162_rn(v0 - __bfloat162float(h.x),
                                                         v1 - __bfloat162float(h.y));
                *(uint32_t*)(Oh + (size_t)r * Nn + col) = *(uint32_t*)&h;
                *(uint32_t*)(Ol + (size_t)r * Nn + col) = *(uint32_t*)&l;
            }
        }
}

// ===========================================================================
// Batched output projections: pre[z] @ W[z]^T + b[z]. grid (4, 32, 4).
// ===========================================================================
struct ProjArgs {
    const float* A[4];
    const float* B[4];
    const float* bias[4];
    float*       C[4];
};
__global__ void __launch_bounds__(256) hm_proj(ProjArgs P)
{
    extern __shared__ char sm[];
    const uint32_t sb = smem_u32(sm);
    const int tid = threadIdx.x, lane = tid & 31, wid = tid >> 5;
    const int warp_m = wid >> 2, warp_n = wid & 3;
    const int K = 512, Nn = 512;
    const int z = blockIdx.z;

    const float* Ab = P.A[z] + (size_t)(blockIdx.y * 128) * K;
    const float* Bb = P.B[z] + (size_t)(blockIdx.x * 128) * K;
    const float* bias = P.bias[z];
    float* C = P.C[z];

    float acc[4][4][4];
#pragma unroll
    for (int i = 0; i < 4; i++)
#pragma unroll
        for (int j = 0; j < 4; j++)
#pragma unroll
            for (int e = 0; e < 4; e++) acc[i][j][e] = 0.f;

    gemm_mainloop(acc, Ab, Bb, K, sm, sb, tid, lane, warp_m, warp_n);

#pragma unroll
    for (int mt = 0; mt < 4; mt++)
#pragma unroll
        for (int nt = 0; nt < 4; nt++) {
            int row = blockIdx.y * 128 + warp_m * 64 + mt * 16 + (lane >> 2);
            int col = blockIdx.x * 128 + warp_n * 32 + nt * 8 + ((lane & 3) << 1);
            float b0 = bias[col], b1 = bias[col + 1];
            float2 v0, v1;
            v0.x = acc[mt][nt][0] + b0; v0.y = acc[mt][nt][1] + b1;
            v1.x = acc[mt][nt][2] + b0; v1.y = acc[mt][nt][3] + b1;
            *(float2*)(C + (size_t)row * Nn + col) = v0;
            *(float2*)(C + (size_t)(row + 8) * Nn + col) = v1;
        }
}

// ===========================================================================
// Ortho loss from bf16 hi/lo qkv. grid (8, 8, 64), 256 thr.
// smem: Ah/Al/Bh/Bl tiles 128x64 halves, stride 144B; + inv norms.
// ===========================================================================
#define OT_TILE 18432           // 128 * 144
#define ORTHO_SMEM (4 * OT_TILE + 1024)

__global__ void __launch_bounds__(256) hm_ortho(
    const __nv_bfloat16* __restrict__ q1h, const __nv_bfloat16* __restrict__ q1l,
    const __nv_bfloat16* __restrict__ q2h, const __nv_bfloat16* __restrict__ q2l,
    float* __restrict__ part)
{
    extern __shared__ char sm[];
    const uint32_t sb = smem_u32(sm);
    float* inva = (float*)(sm + 4 * OT_TILE);
    float* invb = (float*)(sm + 4 * OT_TILE + 512);

    const int tid = threadIdx.x, lane = tid & 31, wid = tid >> 5;
    const int warp_m = wid >> 2, warp_n = wid & 3;

    const int z = blockIdx.z;
    const int bh = z & 31;
    const int b = bh >> 3, h = bh & 7;
    const __nv_bfloat16* baseh = (z < 32) ? q1h : q2h;
    const __nv_bfloat16* basel = (z < 32) ? q1l : q2l;
    const size_t hoff = (size_t)b * 1024 * 2048 + h * 64;
    const int i0 = blockIdx.y * 128, j0 = blockIdx.x * 128;
    // A = q rows i0.., B = qt rows j0.. (+1536 halves)
    const __nv_bfloat16* Ah_g = baseh + hoff + (size_t)i0 * 2048;
    const __nv_bfloat16* Al_g = basel + hoff + (size_t)i0 * 2048;
    const __nv_bfloat16* Bh_g = baseh + hoff + 1536 + (size_t)j0 * 2048;
    const __nv_bfloat16* Bl_g = basel + hoff + 1536 + (size_t)j0 * 2048;

    // load 4 tiles: 128 rows x 8 segs each => 4096 segs / 256 thr = 16
#pragma unroll
    for (int l = 0; l < 16; l++) {
        int idx = tid + l * 256;
        int tile = idx >> 10, r = (idx >> 3) & 127, s = idx & 7;
        const __nv_bfloat16* src =
            (tile == 0) ? Ah_g : (tile == 1) ? Al_g : (tile == 2) ? Bh_g : Bl_g;
        uint4 v = *(const uint4*)(src + (size_t)r * 2048 + s * 8);
        *(uint4*)(sm + tile * OT_TILE + r * 144 + s * 16) = v;
    }
    __syncthreads();

    // row norms from hi+lo
    {
        int tile = (tid < 128) ? 0 : 2;
        int r = tid & 127;
        const __nv_bfloat16* ph = (const __nv_bfloat16*)(sm + tile * OT_TILE + r * 144);
        const __nv_bfloat16* pl = (const __nv_bfloat16*)(sm + (tile + 1) * OT_TILE + r * 144);
        float ssq = 0.f;
#pragma unroll
        for (int c = 0; c < 64; c++) {
            float v = __bfloat162float(ph[c]) + __bfloat162float(pl[c]);
            ssq += v * v;
        }
        float inv = 1.f / fmaxf(sqrtf(ssq), 1e-12f);
        if (tid < 128) inva[r] = inv;
        else           invb[r] = inv;
    }
    __syncthreads();

    float acc[4][4][4];
#pragma unroll
    for (int i = 0; i < 4; i++)
#pragma unroll
        for (int j = 0; j < 4; j++)
#pragma unroll
            for (int e = 0; e < 4; e++) acc[i][j][e] = 0.f;

#pragma unroll
    for (int ks = 0; ks < 4; ks++) {
        uint32_t Af[4][4], Alf[4][4], Bf[2][4], Blf[2][4];
#pragma unroll
        for (int mt = 0; mt < 4; mt++) {
            uint32_t addr = sb + (warp_m * 64 + mt * 16 + (lane & 15)) * 144
                          + ks * 32 + ((lane >> 4) << 4);
            ldsm4(Af[mt], addr);
            ldsm4(Alf[mt], addr + OT_TILE);
        }
#pragma unroll
        for (int np = 0; np < 2; np++) {
            int q3 = lane >> 3;
            int rown = warp_n * 32 + np * 16 + ((q3 >> 1) << 3) + (lane & 7);
            uint32_t addr = sb + 2 * OT_TILE + rown * 144 + ks * 32 + ((q3 & 1) << 4);
            ldsm4(Bf[np], addr);
            ldsm4(Blf[np], addr + OT_TILE);
        }
#pragma unroll
        for (int mt = 0; mt < 4; mt++)
#pragma unroll
            for (int nt = 0; nt < 4; nt++) {
                uint32_t bh0 = Bf[nt >> 1][(nt & 1) * 2];
                uint32_t bh1 = Bf[nt >> 1][(nt & 1) * 2 + 1];
                uint32_t bl0 = Blf[nt >> 1][(nt & 1) * 2];
                uint32_t bl1 = Blf[nt >> 1][(nt & 1) * 2 + 1];
                mma16816(acc[mt][nt], Af[mt], bh0, bh1);
                mma16816(acc[mt][nt], Af[mt], bl0, bl1);
                mma16816(acc[mt][nt], Alf[mt], bh0, bh1);
            }
    }

    float ssum = 0.f;
#pragma unroll
    for (int mt = 0; mt < 4; mt++)
#pragma unroll
        for (int nt = 0; nt < 4; nt++) {
            int r = warp_m * 64 + mt * 16 + (lane >> 2);
            int c = warp_n * 32 + nt * 8 + ((lane & 3) << 1);
            int gi0 = i0 + r, gi1 = gi0 + 8;
            int gj0 = j0 + c, gj1 = gj0 + 1;
            float ia0 = inva[r], ia1 = inva[r + 8];
            float ib0 = invb[c], ib1 = invb[c + 1];
            float g00 = acc[mt][nt][0] * ia0 * ib0;
            float g01 = acc[mt][nt][1] * ia0 * ib1;
            float g10 = acc[mt][nt][2] * ia1 * ib0;
            float g11 = acc[mt][nt][3] * ia1 * ib1;
            if (gi0 != gj0) ssum += g00 * g00;
            if (gi0 != gj1) ssum += g01 * g01;
            if (gi1 != gj0) ssum += g10 * g10;
            if (gi1 != gj1) ssum += g11 * g11;
        }

    __syncthreads();
    float* rb = (float*)sm;
    rb[tid] = ssum;
    __syncthreads();
    for (int st = 128; st > 0; st >>= 1) {
        if (tid < st) rb[tid] += rb[tid + st];
        __syncthreads();
    }
    if (tid == 0)
        part[(size_t)z * 64 + blockIdx.y * 8 + blockIdx.x] = rb[0];
}

// ===========================================================================
// HMMA flash attention: bf16 hi/lo in, fp32 out.
// CTA: 128 queries, 8 warps x 16 rows; key tiles of 32, 32 iters.
// grid (8, 32, 4), 256 thr.
// smem: Q hi/lo [128][72 halves] + K/V hi/lo [32][72 halves]
// ===========================================================================
struct AttnArgs {
    const __nv_bfloat16* qh[4]; const __nv_bfloat16* ql[4];
    const __nv_bfloat16* kh[4]; const __nv_bfloat16* kl[4];
    const __nv_bfloat16* vh[4]; const __nv_bfloat16* vl[4];
    float* o[4];
};
#define AQ_TILE 18432            // 128*144
#define AKV_TILE 4608            // 32*144
#define ATTN_SMEM (2 * AQ_TILE + 4 * AKV_TILE)   // 55296

__global__ void __launch_bounds__(256) attn_hmma(AttnArgs P)
{
    extern __shared__ char sm[];
    const uint32_t sb = smem_u32(sm);
    const int tid = threadIdx.x, lane = tid & 31, w = tid >> 5;

    const int z = blockIdx.z;
    const int bh = blockIdx.y;
    const int qt = blockIdx.x;
    const int b = bh >> 3, h = bh & 7;
    const size_t hoff = (size_t)b * 1024 * 2048 + h * 64;

    const __nv_bfloat16* qh_g = P.qh[z] + hoff;
    const __nv_bfloat16* ql_g = P.ql[z] + hoff;
    const __nv_bfloat16* kh_g = P.kh[z] + hoff;
    const __nv_bfloat16* kl_g = P.kl[z] + hoff;
    const __nv_bfloat16* vh_g = P.vh[z] + hoff;
    const __nv_bfloat16* vl_g = P.vl[z] + hoff;
    float* og = P.o[z] + (size_t)(b * 1024 + qt * 128) * 512 + h * 64;

    const uint32_t sQ = sb;                  // Qh, Ql at +AQ_TILE
    const uint32_t sK = sb + 2 * AQ_TILE;    // Kh, Kl, Vh, Vl (AKV_TILE apart)

    // ---- Prologue: stage Q tile (hi/lo), load Q fragments to registers ----
#pragma unroll
    for (int l = 0; l < 8; l++) {
        int idx = tid + l * 256;
        int buf = idx >> 10, r = (idx >> 3) & 127, s = idx & 7;
        const __nv_bfloat16* src = buf ? ql_g : qh_g;
        uint4 v = *(const uint4*)(src + (size_t)(qt * 128 + r) * 2048 + s * 8);
        *(uint4*)(sm + buf * AQ_TILE + r * 144 + s * 16) = v;
    }
    __syncthreads();

    uint32_t Qh[4][4], Ql[4][4];
#pragma unroll
    for (int ks = 0; ks < 4; ks++) {
        uint32_t addr = sQ + (w * 16 + (lane & 15)) * 144 + ks * 32 + ((lane >> 4) << 4);
        ldsm4(Qh[ks], addr);
        ldsm4(Ql[ks], addr + AQ_TILE);
    }

    float oacc[8][4];
#pragma unroll
    for (int f = 0; f < 8; f++)
#pragma unroll
        for (int e = 0; e < 4; e++) oacc[f][e] = 0.f;
    float m0 = -1e30f, m1 = -1e30f, l0 = 0.f, l1 = 0.f;

    for (int t = 0; t < 32; t++) {
        __syncthreads();   // previous iteration's reads done
        // load K/V hi/lo tile (32 keys): 4 tiles x 32 rows x 8 segs = 1024/256
        {
            int r = tid >> 3, s = tid & 7;
            size_t go = (size_t)(t * 32 + r) * 2048 + s * 8;
            uint32_t so = r * 144 + s * 16;
            *(uint4*)(sm + 2 * AQ_TILE + so)                = *(const uint4*)(kh_g + go);
            *(uint4*)(sm + 2 * AQ_TILE + AKV_TILE + so)     = *(const uint4*)(kl_g + go);
            *(uint4*)(sm + 2 * AQ_TILE + 2 * AKV_TILE + so) = *(const uint4*)(vh_g + go);
            *(uint4*)(sm + 2 * AQ_TILE + 3 * AKV_TILE + so) = *(const uint4*)(vl_g + go);
        }
        __syncthreads();

        // ---- S = Q K^T (16 x 32 per warp), 3-term split ----
        float sacc[4][4];
#pragma unroll
        for (int nf = 0; nf < 4; nf++)
#pragma unroll
            for (int e = 0; e < 4; e++) sacc[nf][e] = 0.f;
#pragma unroll
        for (int ks = 0; ks < 4; ks++) {
            uint32_t Kh[2][4], Kl[2][4];
#pragma unroll
            for (int np = 0; np < 2; np++) {
                int q3 = lane >> 3;
                int rown = np * 16 + ((q3 >> 1) << 3) + (lane & 7);
                uint32_t addr = sK + rown * 144 + ks * 32 + ((q3 & 1) << 4);
                ldsm4(Kh[np], addr);
                ldsm4(Kl[np], addr + AKV_TILE);
            }
#pragma unroll
            for (int nf = 0; nf < 4; nf++) {
                uint32_t bh0 = Kh[nf >> 1][(nf & 1) * 2];
                uint32_t bh1 = Kh[nf >> 1][(nf & 1) * 2 + 1];
                uint32_t bl0 = Kl[nf >> 1][(nf & 1) * 2];
                uint32_t bl1 = Kl[nf >> 1][(nf & 1) * 2 + 1];
                mma16816(sacc[nf], Qh[ks], bh0, bh1);
                mma16816(sacc[nf], Qh[ks], bl0, bl1);
                mma16816(sacc[nf], Ql[ks], bh0, bh1);
            }
        }
#pragma unroll
        for (int nf = 0; nf < 4; nf++)
#pragma unroll
            for (int e = 0; e < 4; e++) sacc[nf][e] *= 0.125f;

        // ---- online softmax (rows r = w*16 + lane>>2, and +8) ----
        float tm0 = -1e30f, tm1 = -1e30f;
#pragma unroll
        for (int nf = 0; nf < 4; nf++) {
            tm0 = fmaxf(tm0, fmaxf(sacc[nf][0], sacc[nf][1]));
            tm1 = fmaxf(tm1, fmaxf(sacc[nf][2], sacc[nf][3]));
        }
        tm0 = fmaxf(tm0, __shfl_xor_sync(0xFFFFFFFFu, tm0, 1));
        tm0 = fmaxf(tm0, __shfl_xor_sync(0xFFFFFFFFu, tm0, 2));
        tm1 = fmaxf(tm1, __shfl_xor_sync(0xFFFFFFFFu, tm1, 1));
        tm1 = fmaxf(tm1, __shfl_xor_sync(0xFFFFFFFFu, tm1, 2));
        float mn0 = fmaxf(m0, tm0), mn1 = fmaxf(m1, tm1);
        float sc0 = __expf(m0 - mn0), sc1 = __expf(m1 - mn1);
        m0 = mn0; m1 = mn1;

        float p[4][4];
        float rs0 = 0.f, rs1 = 0.f;
#pragma unroll
        for (int nf = 0; nf < 4; nf++) {
            p[nf][0] = __expf(sacc[nf][0] - mn0);
            p[nf][1] = __expf(sacc[nf][1] - mn0);
            p[nf][2] = __expf(sacc[nf][2] - mn1);
            p[nf][3] = __expf(sacc[nf][3] - mn1);
            rs0 += p[nf][0] + p[nf][1];
            rs1 += p[nf][2] + p[nf][3];
        }
        rs0 += __shfl_xor_sync(0xFFFFFFFFu, rs0, 1);
        rs0 += __shfl_xor_sync(0xFFFFFFFFu, rs0, 2);
        rs1 += __shfl_xor_sync(0xFFFFFFFFu, rs1, 1);
        rs1 += __shfl_xor_sync(0xFFFFFFFFu, rs1, 2);
        l0 = l0 * sc0 + rs0;
        l1 = l1 * sc1 + rs1;

#pragma unroll
        for (int f = 0; f < 8; f++) {
            oacc[f][0] *= sc0; oacc[f][1] *= sc0;
            oacc[f][2] *= sc1; oacc[f][3] *= sc1;
        }

        // ---- P fragments (bf16 hi/lo split), A-layout for PV ----
        uint32_t Ph[2][4], Pl[2][4];
#pragma unroll
        for (int ks2 = 0; ks2 < 2; ks2++) {
#pragma unroll
            for (int j = 0; j < 2; j++) {        // nfrag 2*ks2 + j
                int nf = 2 * ks2 + j;
#pragma unroll
                for (int hp = 0; hp < 2; hp++) { // row half: 0 -> (c0,c1), 1 -> (c2,c3)
                    float v0 = p[nf][hp * 2], v1 = p[nf][hp * 2 + 1];
                    __nv_bfloat162 hh = __floats2bfloat162_rn(v0, v1);
                    __nv_bfloat162 ll = __floats2bfloat162_rn(
                        v0 - __bfloat162float(hh.x), v1 - __bfloat162float(hh.y));
                    Ph[ks2][j * 2 + hp] = *(uint32_t*)&hh;
                    Pl[ks2][j * 2 + hp] = *(uint32_t*)&ll;
                }
            }
        }
        // reorder to A-frag: a0=(r,k0..7)=j0hp0, a1=(r+8,k0..7)=j0hp1,
        //                    a2=(r,k8..15)=j1hp0, a3=(r+8,k8..15)=j1hp1
        // layout above: idx j*2+hp -> [a0=0, a1=1, a2=2, a3=3] already correct.

        // ---- O += P V, V^T via ldmatrix.trans, 3-term split ----
#pragma unroll
        for (int ks2 = 0; ks2 < 2; ks2++) {
#pragma unroll
            for (int np = 0; np < 4; np++) {     // d pairs of 16
                int rowv = ks2 * 16 + (((lane >> 3) & 1) << 3) + (lane & 7);
                int colv = np * 16 + ((lane >> 4) << 3);
                uint32_t addr = sK + 2 * AKV_TILE + rowv * 144 + colv * 2;
                uint32_t Vh[4], Vl[4];
                ldsm4t(Vh, addr);
                ldsm4t(Vl, addr + AKV_TILE);
                mma16816(oacc[2 * np],     Ph[ks2], Vh[0], Vh[1]);
                mma16816(oacc[2 * np],     Ph[ks2], Vl[0], Vl[1]);
                mma16816(oacc[2 * np],     Pl[ks2], Vh[0], Vh[1]);
                mma16816(oacc[2 * np + 1], Ph[ks2], Vh[2], Vh[3]);
                mma16816(oacc[2 * np + 1], Ph[ks2], Vl[2], Vl[3]);
                mma16816(oacc[2 * np + 1], Pl[ks2], Vh[2], Vh[3]);
            }
        }
    }

    // ---- epilogue ----
    float inv0 = 1.f / l0, inv1 = 1.f / l1;
    int r = w * 16 + (lane >> 2);
#pragma unroll
    for (int f = 0; f < 8; f++) {
        int c = f * 8 + ((lane & 3) << 1);
        float2 v0, v1;
        v0.x = oacc[f][0] * inv0; v0.y = oacc[f][1] * inv0;
        v1.x = oacc[f][2] * inv1; v1.y = oacc[f][3] * inv1;
        *(float2*)(og + (size_t)r * 512 + c) = v0;
        *(float2*)(og + (size_t)(r + 8) * 512 + c) = v1;
    }
}

// ---------------------------------------------------------------------------
// lc partials: per row r of xc/yc (post-projection), 1 - cos(xc_n, yc_n)
// ---------------------------------------------------------------------------
__global__ void __launch_bounds__(128) lc_kernel(
    const float* __restrict__ xc, const float* __restrict__ yc,
    float* __restrict__ part)
{
    const int r = blockIdx.x;
    const float* xr = xc + (size_t)r * 512;
    const float* yr = yc + (size_t)r * 512;
    __shared__ float sxx[128], syy[128], sxy[128];
    const int tid = threadIdx.x;
    float xx = 0.f, yy = 0.f, xy = 0.f;
    for (int i = tid; i < 512; i += 128) {
        float xv = xr[i], yv = yr[i];
        xx += xv * xv; yy += yv * yv; xy += xv * yv;
    }
    sxx[tid] = xx; syy[tid] = yy; sxy[tid] = xy;
    __syncthreads();
    for (int st = 64; st > 0; st >>= 1) {
        if (tid < st) {
            sxx[tid] += sxx[tid + st];
            syy[tid] += syy[tid + st];
            sxy[tid] += sxy[tid + st];
        }
        __syncthreads();
    }
    if (tid == 0) {
        float nx = fmaxf(sqrtf(sxx[0]), 1e-12f);
        float ny = fmaxf(sqrtf(syy[0]), 1e-12f);
        part[r] = 1.f - sxy[0] / (nx * ny);
    }
}

// ---------------------------------------------------------------------------
// Deterministic final reductions for the 3 scalars
// ---------------------------------------------------------------------------
__global__ void __launch_bounds__(256) finalize_kernel(
    const float* __restrict__ porth, const float* __restrict__ plc,
    float* __restrict__ outs)
{
    __shared__ float sh[256];
    const int tid = threadIdx.x;

    float s = 0.f;
    for (int i = tid; i < 2048; i += 256) s += porth[i];
    sh[tid] = s; __syncthreads();
    for (int st = 128; st > 0; st >>= 1) { if (tid < st) sh[tid] += sh[tid + st]; __syncthreads(); }
    if (tid == 0) outs[0] = sh[0] * (1.f / 4194304.f);
    __syncthreads();

    s = 0.f;
    for (int i = tid; i < 2048; i += 256) s += porth[2048 + i];
    sh[tid] = s; __syncthreads();
    for (int st = 128; st > 0; st >>= 1) { if (tid < st) sh[tid] += sh[tid + st]; __syncthreads(); }
    if (tid == 0) outs[1] = sh[0] * (1.f / 4194304.f);
    __syncthreads();

    s = 0.f;
    for (int i = tid; i < 4096; i += 256) s += plc[i];
    sh[tid] = s; __syncthreads();
    for (int st = 128; st > 0; st >>= 1) { if (tid < st) sh[tid] += sh[tid + st]; __syncthreads(); }
    if (tid == 0) outs[2] = sh[0] * (1.f / 4096.f);
}

// ---------------------------------------------------------------------------
extern "C" void kernel_launch(void* const* d_in, const int* in_sizes, int n_in,
                              void* d_out, int out_size)
{
    (void)in_sizes; (void)n_in;
    const float* x   = (const float*)d_in[0];
    const float* y   = (const float*)d_in[1];
    const float* Wq1 = (const float*)d_in[2];
    const float* Wq2 = (const float*)d_in[3];
    const float* W[4]  = {(const float*)d_in[4], (const float*)d_in[6],
                          (const float*)d_in[8], (const float*)d_in[10]};
    const float* bb[4] = {(const float*)d_in[5], (const float*)d_in[7],
                          (const float*)d_in[9], (const float*)d_in[11]};
    float* out = (float*)d_out;

    __nv_bfloat16 *q1h, *q1l, *q2h, *q2l;
    float *pre, *porth, *plc;
    cudaGetSymbolAddress((void**)&q1h, g_q1h);
    cudaGetSymbolAddress((void**)&q1l, g_q1l);
    cudaGetSymbolAddress((void**)&q2h, g_q2h);
    cudaGetSymbolAddress((void**)&q2l, g_q2l);
    cudaGetSymbolAddress((void**)&pre, g_pre);
    cudaGetSymbolAddress((void**)&porth, g_part_orth);
    cudaGetSymbolAddress((void**)&plc, g_part_lc);

    cudaFuncSetAttribute(hm_gemm_qkv, cudaFuncAttributeMaxDynamicSharedMemorySize, GEMM_SMEM);
    cudaFuncSetAttribute(hm_proj, cudaFuncAttributeMaxDynamicSharedMemorySize, GEMM_SMEM);
    cudaFuncSetAttribute(hm_ortho, cudaFuncAttributeMaxDynamicSharedMemorySize, ORTHO_SMEM);
    cudaFuncSetAttribute(attn_hmma, cudaFuncAttributeMaxDynamicSharedMemorySize, ATTN_SMEM);

    const int chunk = (out_size - 3) / 4;  // 2097152 = 4096*512

    // QKV projections -> bf16 hi/lo
    hm_gemm_qkv<<<dim3(16, 32), 256, GEMM_SMEM>>>(x, Wq1, q1h, q1l);
    hm_gemm_qkv<<<dim3(16, 32), 256, GEMM_SMEM>>>(y, Wq2, q2h, q2l);

    // Ortho losses
    hm_ortho<<<dim3(8, 8, 64), 256, ORTHO_SMEM>>>(q1h, q1l, q2h, q2l, porth);

    // 4 attentions (HMMA flash):
    //   pre[0]=attn(qy,kx,vx)->xc  pre[1]=attn(qx,ky,vy)->yc
    //   pre[2]=attn(qtx,kx,vx)->xt pre[3]=attn(qty,ky,vy)->yt
    AttnArgs aa;
    // z=0: q from qkv2(off 0), k/v from qkv1(+512/+1024)
    aa.qh[0] = q2h;        aa.ql[0] = q2l;
    aa.kh[0] = q1h + 512;  aa.kl[0] = q1l + 512;
    aa.vh[0] = q1h + 1024; aa.vl[0] = q1l + 1024; aa.o[0] = pre;
    // z=1: q qkv1, k/v qkv2
    aa.qh[1] = q1h;        aa.ql[1] = q1l;
    aa.kh[1] = q2h + 512;  aa.kl[1] = q2l + 512;
    aa.vh[1] = q2h + 1024; aa.vl[1] = q2l + 1024; aa.o[1] = pre + 2097152;
    // z=2: qt of qkv1, k/v qkv1
    aa.qh[2] = q1h + 1536; aa.ql[2] = q1l + 1536;
    aa.kh[2] = q1h + 512;  aa.kl[2] = q1l + 512;
    aa.vh[2] = q1h + 1024; aa.vl[2] = q1l + 1024; aa.o[2] = pre + 2 * 2097152;
    // z=3: qt of qkv2, k/v qkv2
    aa.qh[3] = q2h + 1536; aa.ql[3] = q2l + 1536;
    aa.kh[3] = q2h + 512;  aa.kl[3] = q2l + 512;
    aa.vh[3] = q2h + 1024; aa.vl[3] = q2l + 1024; aa.o[3] = pre + 3 * 2097152;
    attn_hmma<<<dim3(8, 32, 4), 256, ATTN_SMEM>>>(aa);

    // Output projections (batched) straight into d_out (xc, yc, xt, yt)
    ProjArgs pa;
    for (int i = 0; i < 4; i++) {
        pa.A[i] = pre + (size_t)i * 2097152;
        pa.B[i] = W[i];
        pa.bias[i] = bb[i];
        pa.C[i] = out + (size_t)i * chunk;
    }
    hm_proj<<<dim3(4, 32, 4), 256, GEMM_SMEM>>>(pa);

    // lc on post-projection xc, yc
    lc_kernel<<<4096, 128>>>(out, out + chunk, plc);

    // scalars: lorthx, lorthy, lc
    finalize_kernel<<<1, 256>>>(porth, plc, out + (size_t)out_size - 3);
}

// round 7
// speedup vs baseline: 3.4636x; 1.0745x over previous
#include <cuda_runtime.h>
#include <cuda_bf16.h>
#include <math.h>
#include <stdint.h>

// Problem constants: B=4, N=1024, C=512, H=8, HD=64, SCALE=0.125
// qkv bf16 hi/lo layout: [4096 rows = b*1024+seq][2048 cols = which*512 + h*64 + d]

__device__ __nv_bfloat16 g_q1h[4096 * 2048];
__device__ __nv_bfloat16 g_q1l[4096 * 2048];
__device__ __nv_bfloat16 g_q2h[4096 * 2048];
__device__ __nv_bfloat16 g_q2l[4096 * 2048];
__device__ float g_pre[4 * 4096 * 512];
__device__ float g_part_orth[16384];
__device__ float g_part_lc[4096];

// ===========================================================================
// mma.sync machinery (base-target HMMA): bf16 hi/lo split, fp32 accumulate
// ===========================================================================
__device__ __forceinline__ uint32_t smem_u32(const void* p) {
    uint32_t a;
    asm("{ .reg .u64 t; cvta.to.shared.u64 t, %1; cvt.u32.u64 %0, t; }"
        : "=r"(a) : "l"(p));
    return a;
}
__device__ __forceinline__ void ldsm4(uint32_t* r, uint32_t addr) {
    asm volatile("ldmatrix.sync.aligned.m8n8.x4.shared.b16 {%0,%1,%2,%3}, [%4];"
                 : "=r"(r[0]), "=r"(r[1]), "=r"(r[2]), "=r"(r[3]) : "r"(addr));
}
__device__ __forceinline__ void ldsm4t(uint32_t* r, uint32_t addr) {
    asm volatile("ldmatrix.sync.aligned.m8n8.x4.trans.shared.b16 {%0,%1,%2,%3}, [%4];"
                 : "=r"(r[0]), "=r"(r[1]), "=r"(r[2]), "=r"(r[3]) : "r"(addr));
}
__device__ __forceinline__ void mma16816(float* c, const uint32_t* a,
                                         uint32_t b0, uint32_t b1) {
    asm volatile(
        "mma.sync.aligned.m16n8k16.row.col.f32.bf16.bf16.f32 "
        "{%0,%1,%2,%3}, {%4,%5,%6,%7}, {%8,%9}, {%0,%1,%2,%3};"
        : "+f"(c[0]), "+f"(c[1]), "+f"(c[2]), "+f"(c[3])
        : "r"(a[0]), "r"(a[1]), "r"(a[2]), "r"(a[3]), "r"(b0), "r"(b1));
}
__device__ __forceinline__ void cp_async16(uint32_t dst, const void* src) {
    asm volatile("cp.async.cg.shared.global [%0], [%1], 16;"
                 :: "r"(dst), "l"(src));
}
__device__ __forceinline__ void cp_commit() {
    asm volatile("cp.async.commit_group;");
}
template <int N>
__device__ __forceinline__ void cp_wait() {
    asm volatile("cp.async.wait_group %0;" :: "n"(N));
}

// ---------------------------------------------------------------------------
// fp32-input GEMM machinery (80B-stride tiles)
// ---------------------------------------------------------------------------
#define T_STRIDE_B 80
#define T_BYTES    10240
#define BUF_BYTES  40960
#define GEMM_SMEM  (2 * BUF_BYTES)

__device__ __forceinline__ void gload(float4* r, const float* __restrict__ g,
                                      int ld, int tid, int koff) {
#pragma unroll
    for (int l = 0; l < 4; l++) {
        int idx = tid + l * 256;
        int row = idx >> 3, c4 = (idx & 7) << 2;
        r[l] = *(const float4*)(g + (size_t)row * ld + koff + c4);
    }
}
__device__ __forceinline__ void cstore(const float4* r, char* base, int tid) {
#pragma unroll
    for (int l = 0; l < 4; l++) {
        int idx = tid + l * 256;
        int row = idx >> 3, c4 = (idx & 7) << 2;
        float4 v = r[l];
        __nv_bfloat162 h0 = __floats2bfloat162_rn(v.x, v.y);
        __nv_bfloat162 h1 = __floats2bfloat162_rn(v.z, v.w);
        __nv_bfloat162 l0 = __floats2bfloat162_rn(v.x - __bfloat162float(h0.x),
                                                  v.y - __bfloat162float(h0.y));
        __nv_bfloat162 l1 = __floats2bfloat162_rn(v.z - __bfloat162float(h1.x),
                                                  v.w - __bfloat162float(h1.y));
        int off = row * T_STRIDE_B + (c4 << 1);
        uint2 hv, lv;
        hv.x = *(uint32_t*)&h0; hv.y = *(uint32_t*)&h1;
        lv.x = *(uint32_t*)&l0; lv.y = *(uint32_t*)&l1;
        *(uint2*)(base + off) = hv;
        *(uint2*)(base + T_BYTES + off) = lv;
    }
}
__device__ __forceinline__ void compute_chunk(float acc[4][4][4], uint32_t sbuf,
                                              int lane, int warp_m, int warp_n) {
    const uint32_t aBase = sbuf;
    const uint32_t bBase = sbuf + 2 * T_BYTES;
#pragma unroll
    for (int kk = 0; kk < 2; kk++) {
        uint32_t Ah[4][4], Al[4][4], Bh[2][4], Bl[2][4];
#pragma unroll
        for (int mt = 0; mt < 4; mt++) {
            int row = warp_m * 64 + mt * 16 + (lane & 15);
            uint32_t addr = aBase + row * T_STRIDE_B + kk * 32 + ((lane >> 4) << 4);
            ldsm4(Ah[mt], addr);
            ldsm4(Al[mt], addr + T_BYTES);
        }
#pragma unroll
        for (int nt2 = 0; nt2 < 2; nt2++) {
            int q = lane >> 3;
            int rown = warp_n * 32 + nt2 * 16 + ((q >> 1) << 3) + (lane & 7);
            uint32_t addr = bBase + rown * T_STRIDE_B + kk * 32 + ((q & 1) << 4);
            ldsm4(Bh[nt2], addr);
            ldsm4(Bl[nt2], addr + T_BYTES);
        }
#pragma unroll
        for (int mt = 0; mt < 4; mt++)
#pragma unroll
            for (int nt = 0; nt < 4; nt++) {
                uint32_t bh0 = Bh[nt >> 1][(nt & 1) * 2];
                uint32_t bh1 = Bh[nt >> 1][(nt & 1) * 2 + 1];
                uint32_t bl0 = Bl[nt >> 1][(nt & 1) * 2];
                uint32_t bl1 = Bl[nt >> 1][(nt & 1) * 2 + 1];
                mma16816(acc[mt][nt], Ah[mt], bh0, bh1);
                mma16816(acc[mt][nt], Ah[mt], bl0, bl1);
                mma16816(acc[mt][nt], Al[mt], bh0, bh1);
            }
    }
}
__device__ __forceinline__ void gemm_mainloop(
    float acc[4][4][4], const float* Ab, const float* Bb, int K,
    char* sm, uint32_t sb, int tid, int lane, int warp_m, int warp_n)
{
    const int nch = K >> 5;
    float4 ar[4], br[4];
    gload(ar, Ab, K, tid, 0);
    gload(br, Bb, K, tid, 0);
    cstore(ar, sm, tid);
    cstore(br, sm + 2 * T_BYTES, tid);
    __syncthreads();
    int s = 0;
    for (int ch = 0; ch < nch; ch++) {
        const bool pre = (ch + 1 < nch);
        if (pre) {
            gload(ar, Ab, K, tid, (ch + 1) * 32);
            gload(br, Bb, K, tid, (ch + 1) * 32);
        }
        compute_chunk(acc, sb + s * BUF_BYTES, lane, warp_m, warp_n);
        if (pre) {
            char* nb = sm + (s ^ 1) * BUF_BYTES;
            cstore(ar, nb, tid);
            cstore(br, nb + 2 * T_BYTES, tid);
        }
        __syncthreads();
        s ^= 1;
    }
}

// ===========================================================================
// QKV projections, both in one launch: fp32 in, bf16 hi/lo out.
// grid (16, 32, 2), 256 thr.
// ===========================================================================
struct QkvArgs {
    const float* A[2];
    const float* B[2];
    __nv_bfloat16* Oh[2];
    __nv_bfloat16* Ol[2];
};
__global__ void __launch_bounds__(256) hm_gemm_qkv(QkvArgs P)
{
    extern __shared__ char sm[];
    const uint32_t sb = smem_u32(sm);
    const int tid = threadIdx.x, lane = tid & 31, wid = tid >> 5;
    const int warp_m = wid >> 2, warp_n = wid & 3;
    const int K = 512, Nn = 2048;
    const int z = blockIdx.z;

    const float* Ab = P.A[z] + (size_t)(blockIdx.y * 128) * K;
    const float* Bb = P.B[z] + (size_t)(blockIdx.x * 128) * K;
    __nv_bfloat16* Oh = P.Oh[z];
    __nv_bfloat16* Ol = P.Ol[z];

    float acc[4][4][4];
#pragma unroll
    for (int i = 0; i < 4; i++)
#pragma unroll
        for (int j = 0; j < 4; j++)
#pragma unroll
            for (int e = 0; e < 4; e++) acc[i][j][e] = 0.f;

    gemm_mainloop(acc, Ab, Bb, K, sm, sb, tid, lane, warp_m, warp_n);

#pragma unroll
    for (int mt = 0; mt < 4; mt++)
#pragma unroll
        for (int nt = 0; nt < 4; nt++) {
            int row = blockIdx.y * 128 + warp_m * 64 + mt * 16 + (lane >> 2);
            int col = blockIdx.x * 128 + warp_n * 32 + nt * 8 + ((lane & 3) << 1);
#pragma unroll
            for (int half = 0; half < 2; half++) {
                float v0 = acc[mt][nt][half * 2], v1 = acc[mt][nt][half * 2 + 1];
                int r = row + half * 8;
                __nv_bfloat162 h = __floats2bfloat162_rn(v0, v1);
                __nv_bfloat162 l = __floats2bfloat162_rn(v0 - __bfloat162float(h.x),
                                                         v1 - __bfloat162float(h.y));
                *(uint32_t*)(Oh + (size_t)r * Nn + col) = *(uint32_t*)&h;
                *(uint32_t*)(Ol + (size_t)r * Nn + col) = *(uint32_t*)&l;
            }
        }
}

// ===========================================================================
// Batched output projections: pre[z] @ W[z]^T + b[z]. grid (4, 32, 4).
// ===========================================================================
struct ProjArgs {
    const float* A[4];
    const float* B[4];
    const float* bias[4];
    float*       C[4];
};
__global__ void __launch_bounds__(256) hm_proj(ProjArgs P)
{
    extern __shared__ char sm[];
    const uint32_t sb = smem_u32(sm);
    const int tid = threadIdx.x, lane = tid & 31, wid = tid >> 5;
    const int warp_m = wid >> 2, warp_n = wid & 3;
    const int K = 512, Nn = 512;
    const int z = blockIdx.z;

    const float* Ab = P.A[z] + (size_t)(blockIdx.y * 128) * K;
    const float* Bb = P.B[z] + (size_t)(blockIdx.x * 128) * K;
    const float* bias = P.bias[z];
    float* C = P.C[z];

    float acc[4][4][4];
#pragma unroll
    for (int i = 0; i < 4; i++)
#pragma unroll
        for (int j = 0; j < 4; j++)
#pragma unroll
            for (int e = 0; e < 4; e++) acc[i][j][e] = 0.f;

    gemm_mainloop(acc, Ab, Bb, K, sm, sb, tid, lane, warp_m, warp_n);

#pragma unroll
    for (int mt = 0; mt < 4; mt++)
#pragma unroll
        for (int nt = 0; nt < 4; nt++) {
            int row = blockIdx.y * 128 + warp_m * 64 + mt * 16 + (lane >> 2);
            int col = blockIdx.x * 128 + warp_n * 32 + nt * 8 + ((lane & 3) << 1);
            float b0 = bias[col], b1 = bias[col + 1];
            float2 v0, v1;
            v0.x = acc[mt][nt][0] + b0; v0.y = acc[mt][nt][1] + b1;
            v1.x = acc[mt][nt][2] + b0; v1.y = acc[mt][nt][3] + b1;
            *(float2*)(C + (size_t)row * Nn + col) = v0;
            *(float2*)(C + (size_t)(row + 8) * Nn + col) = v1;
        }
}

// ===========================================================================
// Ortho loss from bf16 hi/lo qkv. grid (8, 8, 64), 256 thr.
// ===========================================================================
#define OT_TILE 18432           // 128 * 144
#define ORTHO_SMEM (4 * OT_TILE + 1024)

__global__ void __launch_bounds__(256) hm_ortho(
    const __nv_bfloat16* __restrict__ q1h, const __nv_bfloat16* __restrict__ q1l,
    const __nv_bfloat16* __restrict__ q2h, const __nv_bfloat16* __restrict__ q2l,
    float* __restrict__ part)
{
    extern __shared__ char sm[];
    const uint32_t sb = smem_u32(sm);
    float* inva = (float*)(sm + 4 * OT_TILE);
    float* invb = (float*)(sm + 4 * OT_TILE + 512);

    const int tid = threadIdx.x, lane = tid & 31, wid = tid >> 5;
    const int warp_m = wid >> 2, warp_n = wid & 3;

    const int z = blockIdx.z;
    const int bh = z & 31;
    const int b = bh >> 3, h = bh & 7;
    const __nv_bfloat16* baseh = (z < 32) ? q1h : q2h;
    const __nv_bfloat16* basel = (z < 32) ? q1l : q2l;
    const size_t hoff = (size_t)b * 1024 * 2048 + h * 64;
    const int i0 = blockIdx.y * 128, j0 = blockIdx.x * 128;
    const __nv_bfloat16* Ah_g = baseh + hoff + (size_t)i0 * 2048;
    const __nv_bfloat16* Al_g = basel + hoff + (size_t)i0 * 2048;
    const __nv_bfloat16* Bh_g = baseh + hoff + 1536 + (size_t)j0 * 2048;
    const __nv_bfloat16* Bl_g = basel + hoff + 1536 + (size_t)j0 * 2048;

#pragma unroll
    for (int l = 0; l < 16; l++) {
        int idx = tid + l * 256;
        int tile = idx >> 10, r = (idx >> 3) & 127, s = idx & 7;
        const __nv_bfloat16* src =
            (tile == 0) ? Ah_g : (tile == 1) ? Al_g : (tile == 2) ? Bh_g : Bl_g;
        cp_async16(sb + tile * OT_TILE + r * 144 + s * 16, src + (size_t)r * 2048 + s * 8);
    }
    cp_commit();
    cp_wait<0>();
    __syncthreads();

    // row norms from hi+lo
    {
        int tile = (tid < 128) ? 0 : 2;
        int r = tid & 127;
        const __nv_bfloat16* ph = (const __nv_bfloat16*)(sm + tile * OT_TILE + r * 144);
        const __nv_bfloat16* pl = (const __nv_bfloat16*)(sm + (tile + 1) * OT_TILE + r * 144);
        float ssq = 0.f;
#pragma unroll
        for (int c = 0; c < 64; c++) {
            float v = __bfloat162float(ph[c]) + __bfloat162float(pl[c]);
            ssq += v * v;
        }
        float inv = 1.f / fmaxf(sqrtf(ssq), 1e-12f);
        if (tid < 128) inva[r] = inv;
        else           invb[r] = inv;
    }
    __syncthreads();

    float acc[4][4][4];
#pragma unroll
    for (int i = 0; i < 4; i++)
#pragma unroll
        for (int j = 0; j < 4; j++)
#pragma unroll
            for (int e = 0; e < 4; e++) acc[i][j][e] = 0.f;

#pragma unroll
    for (int ks = 0; ks < 4; ks++) {
        uint32_t Af[4][4], Alf[4][4], Bf[2][4], Blf[2][4];
#pragma unroll
        for (int mt = 0; mt < 4; mt++) {
            uint32_t addr = sb + (warp_m * 64 + mt * 16 + (lane & 15)) * 144
                          + ks * 32 + ((lane >> 4) << 4);
            ldsm4(Af[mt], addr);
            ldsm4(Alf[mt], addr + OT_TILE);
        }
#pragma unroll
        for (int np = 0; np < 2; np++) {
            int q3 = lane >> 3;
            int rown = warp_n * 32 + np * 16 + ((q3 >> 1) << 3) + (lane & 7);
            uint32_t addr = sb + 2 * OT_TILE + rown * 144 + ks * 32 + ((q3 & 1) << 4);
            ldsm4(Bf[np], addr);
            ldsm4(Blf[np], addr + OT_TILE);
        }
#pragma unroll
        for (int mt = 0; mt < 4; mt++)
#pragma unroll
            for (int nt = 0; nt < 4; nt++) {
                uint32_t bh0 = Bf[nt >> 1][(nt & 1) * 2];
                uint32_t bh1 = Bf[nt >> 1][(nt & 1) * 2 + 1];
                uint32_t bl0 = Blf[nt >> 1][(nt & 1) * 2];
                uint32_t bl1 = Blf[nt >> 1][(nt & 1) * 2 + 1];
                mma16816(acc[mt][nt], Af[mt], bh0, bh1);
                mma16816(acc[mt][nt], Af[mt], bl0, bl1);
                mma16816(acc[mt][nt], Alf[mt], bh0, bh1);
            }
    }

    float ssum = 0.f;
#pragma unroll
    for (int mt = 0; mt < 4; mt++)
#pragma unroll
        for (int nt = 0; nt < 4; nt++) {
            int r = warp_m * 64 + mt * 16 + (lane >> 2);
            int c = warp_n * 32 + nt * 8 + ((lane & 3) << 1);
            int gi0 = i0 + r, gi1 = gi0 + 8;
            int gj0 = j0 + c, gj1 = gj0 + 1;
            float ia0 = inva[r], ia1 = inva[r + 8];
            float ib0 = invb[c], ib1 = invb[c + 1];
            float g00 = acc[mt][nt][0] * ia0 * ib0;
            float g01 = acc[mt][nt][1] * ia0 * ib1;
            float g10 = acc[mt][nt][2] * ia1 * ib0;
            float g11 = acc[mt][nt][3] * ia1 * ib1;
            if (gi0 != gj0) ssum += g00 * g00;
            if (gi0 != gj1) ssum += g01 * g01;
            if (gi1 != gj0) ssum += g10 * g10;
            if (gi1 != gj1) ssum += g11 * g11;
        }

    __syncthreads();
    float* rb = (float*)sm;
    rb[tid] = ssum;
    __syncthreads();
    for (int st = 128; st > 0; st >>= 1) {
        if (tid < st) rb[tid] += rb[tid + st];
        __syncthreads();
    }
    if (tid == 0)
        part[(size_t)z * 64 + blockIdx.y * 8 + blockIdx.x] = rb[0];
}

// ===========================================================================
// HMMA flash attention with cp.async double-buffered K/V.
// CTA: 128 queries, 8 warps x 16 rows; key tiles of 32, 32 iters.
// grid (8, 32, 4), 256 thr.
// smem: Q hi/lo (2 x 18432) + 2 KV stages (each Kh/Kl/Vh/Vl x 4608)
// ===========================================================================
struct AttnArgs {
    const __nv_bfloat16* qh[4]; const __nv_bfloat16* ql[4];
    const __nv_bfloat16* kh[4]; const __nv_bfloat16* kl[4];
    const __nv_bfloat16* vh[4]; const __nv_bfloat16* vl[4];
    float* o[4];
};
#define AQ_TILE 18432            // 128*144
#define AKV_TILE 4608            // 32*144
#define AKV_STAGE (4 * AKV_TILE) // 18432
#define ATTN_SMEM (2 * AQ_TILE + 2 * AKV_STAGE)   // 73728

__global__ void __launch_bounds__(256) attn_hmma(AttnArgs P)
{
    extern __shared__ char sm[];
    const uint32_t sb = smem_u32(sm);
    const int tid = threadIdx.x, lane = tid & 31, w = tid >> 5;

    const int z = blockIdx.z;
    const int bh = blockIdx.y;
    const int qt = blockIdx.x;
    const int b = bh >> 3, h = bh & 7;
    const size_t hoff = (size_t)b * 1024 * 2048 + h * 64;

    const __nv_bfloat16* qh_g = P.qh[z] + hoff;
    const __nv_bfloat16* ql_g = P.ql[z] + hoff;
    const __nv_bfloat16* kh_g = P.kh[z] + hoff;
    const __nv_bfloat16* kl_g = P.kl[z] + hoff;
    const __nv_bfloat16* vh_g = P.vh[z] + hoff;
    const __nv_bfloat16* vl_g = P.vl[z] + hoff;
    float* og = P.o[z] + (size_t)(b * 1024 + qt * 128) * 512 + h * 64;

    const uint32_t sQ = sb;
    const uint32_t sKV = sb + 2 * AQ_TILE;

    // KV prefetch for tile t into stage buffer
    const int kr = tid >> 3, kseg = tid & 7;
    const uint32_t kso = kr * 144 + kseg * 16;
    const size_t kgo_base = (size_t)kr * 2048 + kseg * 8;

    // ---- Prologue: stage Q tile (hi/lo) via cp.async, prefetch KV tile 0 ----
#pragma unroll
    for (int l = 0; l < 8; l++) {
        int idx = tid + l * 256;
        int buf = idx >> 10, r = (idx >> 3) & 127, s = idx & 7;
        const __nv_bfloat16* src = buf ? ql_g : qh_g;
        cp_async16(sQ + buf * AQ_TILE + r * 144 + s * 16,
                   src + (size_t)(qt * 128 + r) * 2048 + s * 8);
    }
    cp_commit();
    {
        size_t go = kgo_base;   // t=0
        cp_async16(sKV + kso,                go + kh_g);
        cp_async16(sKV + AKV_TILE + kso,     go + kl_g);
        cp_async16(sKV + 2 * AKV_TILE + kso, go + vh_g);
        cp_async16(sKV + 3 * AKV_TILE + kso, go + vl_g);
    }
    cp_commit();

    cp_wait<1>();   // Q ready
    __syncthreads();
    uint32_t Qh[4][4], Ql[4][4];
#pragma unroll
    for (int ks = 0; ks < 4; ks++) {
        uint32_t addr = sQ + (w * 16 + (lane & 15)) * 144 + ks * 32 + ((lane >> 4) << 4);
        ldsm4(Qh[ks], addr);
        ldsm4(Ql[ks], addr + AQ_TILE);
    }

    float oacc[8][4];
#pragma unroll
    for (int f = 0; f < 8; f++)
#pragma unroll
        for (int e = 0; e < 4; e++) oacc[f][e] = 0.f;
    float m0 = -1e30f, m1 = -1e30f, l0 = 0.f, l1 = 0.f;

    for (int t = 0; t < 32; t++) {
        // prefetch next KV tile into the other stage
        if (t + 1 < 32) {
            uint32_t st = sKV + ((t + 1) & 1) * AKV_STAGE;
            size_t go = kgo_base + (size_t)(t + 1) * 32 * 2048;
            cp_async16(st + kso,                go + kh_g);
            cp_async16(st + AKV_TILE + kso,     go + kl_g);
            cp_async16(st + 2 * AKV_TILE + kso, go + vh_g);
            cp_async16(st + 3 * AKV_TILE + kso, go + vl_g);
            cp_commit();
            cp_wait<1>();
        } else {
            cp_wait<0>();
        }
        __syncthreads();
        const uint32_t sK = sKV + (t & 1) * AKV_STAGE;

        // ---- S = Q K^T (16 x 32 per warp), 3-term split ----
        float sacc[4][4];
#pragma unroll
        for (int nf = 0; nf < 4; nf++)
#pragma unroll
            for (int e = 0; e < 4; e++) sacc[nf][e] = 0.f;
#pragma unroll
        for (int ks = 0; ks < 4; ks++) {
            uint32_t Kh[2][4], Kl[2][4];
#pragma unroll
            for (int np = 0; np < 2; np++) {
                int q3 = lane >> 3;
                int rown = np * 16 + ((q3 >> 1) << 3) + (lane & 7);
                uint32_t addr = sK + rown * 144 + ks * 32 + ((q3 & 1) << 4);
                ldsm4(Kh[np], addr);
                ldsm4(Kl[np], addr + AKV_TILE);
            }
#pragma unroll
            for (int nf = 0; nf < 4; nf++) {
                uint32_t bh0 = Kh[nf >> 1][(nf & 1) * 2];
                uint32_t bh1 = Kh[nf >> 1][(nf & 1) * 2 + 1];
                uint32_t bl0 = Kl[nf >> 1][(nf & 1) * 2];
                uint32_t bl1 = Kl[nf >> 1][(nf & 1) * 2 + 1];
                mma16816(sacc[nf], Qh[ks], bh0, bh1);
                mma16816(sacc[nf], Qh[ks], bl0, bl1);
                mma16816(sacc[nf], Ql[ks], bh0, bh1);
            }
        }
#pragma unroll
        for (int nf = 0; nf < 4; nf++)
#pragma unroll
            for (int e = 0; e < 4; e++) sacc[nf][e] *= 0.125f;

        // ---- online softmax (rows r = w*16 + lane>>2, and +8) ----
        float tm0 = -1e30f, tm1 = -1e30f;
#pragma unroll
        for (int nf = 0; nf < 4; nf++) {
            tm0 = fmaxf(tm0, fmaxf(sacc[nf][0], sacc[nf][1]));
            tm1 = fmaxf(tm1, fmaxf(sacc[nf][2], sacc[nf][3]));
        }
        tm0 = fmaxf(tm0, __shfl_xor_sync(0xFFFFFFFFu, tm0, 1));
        tm0 = fmaxf(tm0, __shfl_xor_sync(0xFFFFFFFFu, tm0, 2));
        tm1 = fmaxf(tm1, __shfl_xor_sync(0xFFFFFFFFu, tm1, 1));
        tm1 = fmaxf(tm1, __shfl_xor_sync(0xFFFFFFFFu, tm1, 2));
        float mn0 = fmaxf(m0, tm0), mn1 = fmaxf(m1, tm1);
        float sc0 = __expf(m0 - mn0), sc1 = __expf(m1 - mn1);
        m0 = mn0; m1 = mn1;

        float p[4][4];
        float rs0 = 0.f, rs1 = 0.f;
#pragma unroll
        for (int nf = 0; nf < 4; nf++) {
            p[nf][0] = __expf(sacc[nf][0] - mn0);
            p[nf][1] = __expf(sacc[nf][1] - mn0);
            p[nf][2] = __expf(sacc[nf][2] - mn1);
            p[nf][3] = __expf(sacc[nf][3] - mn1);
            rs0 += p[nf][0] + p[nf][1];
            rs1 += p[nf][2] + p[nf][3];
        }
        rs0 += __shfl_xor_sync(0xFFFFFFFFu, rs0, 1);
        rs0 += __shfl_xor_sync(0xFFFFFFFFu, rs0, 2);
        rs1 += __shfl_xor_sync(0xFFFFFFFFu, rs1, 1);
        rs1 += __shfl_xor_sync(0xFFFFFFFFu, rs1, 2);
        l0 = l0 * sc0 + rs0;
        l1 = l1 * sc1 + rs1;

#pragma unroll
        for (int f = 0; f < 8; f++) {
            oacc[f][0] *= sc0; oacc[f][1] *= sc0;
            oacc[f][2] *= sc1; oacc[f][3] *= sc1;
        }

        // ---- P fragments (bf16 hi/lo split), A-layout for PV ----
        uint32_t Ph[2][4], Pl[2][4];
#pragma unroll
        for (int ks2 = 0; ks2 < 2; ks2++) {
#pragma unroll
            for (int j = 0; j < 2; j++) {
                int nf = 2 * ks2 + j;
#pragma unroll
                for (int hp = 0; hp < 2; hp++) {
                    float v0 = p[nf][hp * 2], v1 = p[nf][hp * 2 + 1];
                    __nv_bfloat162 hh = __floats2bfloat162_rn(v0, v1);
                    __nv_bfloat162 ll = __floats2bfloat162_rn(
                        v0 - __bfloat162float(hh.x), v1 - __bfloat162float(hh.y));
                    Ph[ks2][j * 2 + hp] = *(uint32_t*)&hh;
                    Pl[ks2][j * 2 + hp] = *(uint32_t*)&ll;
                }
            }
        }

        // ---- O += P V, V^T via ldmatrix.trans, 3-term split ----
#pragma unroll
        for (int ks2 = 0; ks2 < 2; ks2++) {
#pragma unroll
            for (int np = 0; np < 4; np++) {
                int rowv = ks2 * 16 + (((lane >> 3) & 1) << 3) + (lane & 7);
                int colv = np * 16 + ((lane >> 4) << 3);
                uint32_t addr = sK + 2 * AKV_TILE + rowv * 144 + colv * 2;
                uint32_t Vh[4], Vl[4];
                ldsm4t(Vh, addr);
                ldsm4t(Vl, addr + AKV_TILE);
                mma16816(oacc[2 * np],     Ph[ks2], Vh[0], Vh[1]);
                mma16816(oacc[2 * np],     Ph[ks2], Vl[0], Vl[1]);
                mma16816(oacc[2 * np],     Pl[ks2], Vh[0], Vh[1]);
                mma16816(oacc[2 * np + 1], Ph[ks2], Vh[2], Vh[3]);
                mma16816(oacc[2 * np + 1], Ph[ks2], Vl[2], Vl[3]);
                mma16816(oacc[2 * np + 1], Pl[ks2], Vh[2], Vh[3]);
            }
        }
        __syncthreads();   // all warps done with stage (t&1) before reuse
    }

    // ---- epilogue ----
    float inv0 = 1.f / l0, inv1 = 1.f / l1;
    int r = w * 16 + (lane >> 2);
#pragma unroll
    for (int f = 0; f < 8; f++) {
        int c = f * 8 + ((lane & 3) << 1);
        float2 v0, v1;
        v0.x = oacc[f][0] * inv0; v0.y = oacc[f][1] * inv0;
        v1.x = oacc[f][2] * inv1; v1.y = oacc[f][3] * inv1;
        *(float2*)(og + (size_t)r * 512 + c) = v0;
        *(float2*)(og + (size_t)(r + 8) * 512 + c) = v1;
    }
}

// ---------------------------------------------------------------------------
// lc partials: per row r of xc/yc (post-projection), 1 - cos(xc_n, yc_n)
// ---------------------------------------------------------------------------
__global__ void __launch_bounds__(128) lc_kernel(
    const float* __restrict__ xc, const float* __restrict__ yc,
    float* __restrict__ part)
{
    const int r = blockIdx.x;
    const float* xr = xc + (size_t)r * 512;
    const float* yr = yc + (size_t)r * 512;
    __shared__ float sxx[128], syy[128], sxy[128];
    const int tid = threadIdx.x;
    float xx = 0.f, yy = 0.f, xy = 0.f;
    for (int i = tid; i < 512; i += 128) {
        float xv = xr[i], yv = yr[i];
        xx += xv * xv; yy += yv * yv; xy += xv * yv;
    }
    sxx[tid] = xx; syy[tid] = yy; sxy[tid] = xy;
    __syncthreads();
    for (int st = 64; st > 0; st >>= 1) {
        if (tid < st) {
            sxx[tid] += sxx[tid + st];
            syy[tid] += syy[tid + st];
            sxy[tid] += sxy[tid + st];
        }
        __syncthreads();
    }
    if (tid == 0) {
        float nx = fmaxf(sqrtf(sxx[0]), 1e-12f);
        float ny = fmaxf(sqrtf(syy[0]), 1e-12f);
        part[r] = 1.f - sxy[0] / (nx * ny);
    }
}

// ---------------------------------------------------------------------------
// Deterministic final reductions for the 3 scalars
// ---------------------------------------------------------------------------
__global__ void __launch_bounds__(256) finalize_kernel(
    const float* __restrict__ porth, const float* __restrict__ plc,
    float* __restrict__ outs)
{
    __shared__ float sh[256];
    const int tid = threadIdx.x;

    float s = 0.f;
    for (int i = tid; i < 2048; i += 256) s += porth[i];
    sh[tid] = s; __syncthreads();
    for (int st = 128; st > 0; st >>= 1) { if (tid < st) sh[tid] += sh[tid + st]; __syncthreads(); }
    if (tid == 0) outs[0] = sh[0] * (1.f / 4194304.f);
    __syncthreads();

    s = 0.f;
    for (int i = tid; i < 2048; i += 256) s += porth[2048 + i];
    sh[tid] = s; __syncthreads();
    for (int st = 128; st > 0; st >>= 1) { if (tid < st) sh[tid] += sh[tid + st]; __syncthreads(); }
    if (tid == 0) outs[1] = sh[0] * (1.f / 4194304.f);
    __syncthreads();

    s = 0.f;
    for (int i = tid; i < 4096; i += 256) s += plc[i];
    sh[tid] = s; __syncthreads();
    for (int st = 128; st > 0; st >>= 1) { if (tid < st) sh[tid] += sh[tid + st]; __syncthreads(); }
    if (tid == 0) outs[2] = sh[0] * (1.f / 4096.f);
}

// ---------------------------------------------------------------------------
extern "C" void kernel_launch(void* const* d_in, const int* in_sizes, int n_in,
                              void* d_out, int out_size)
{
    (void)in_sizes; (void)n_in;
    const float* x   = (const float*)d_in[0];
    const float* y   = (const float*)d_in[1];
    const float* Wq1 = (const float*)d_in[2];
    const float* Wq2 = (const float*)d_in[3];
    const float* W[4]  = {(const float*)d_in[4], (const float*)d_in[6],
                          (const float*)d_in[8], (const float*)d_in[10]};
    const float* bb[4] = {(const float*)d_in[5], (const float*)d_in[7],
                          (const float*)d_in[9], (const float*)d_in[11]};
    float* out = (float*)d_out;

    __nv_bfloat16 *q1h, *q1l, *q2h, *q2l;
    float *pre, *porth, *plc;
    cudaGetSymbolAddress((void**)&q1h, g_q1h);
    cudaGetSymbolAddress((void**)&q1l, g_q1l);
    cudaGetSymbolAddress((void**)&q2h, g_q2h);
    cudaGetSymbolAddress((void**)&q2l, g_q2l);
    cudaGetSymbolAddress((void**)&pre, g_pre);
    cudaGetSymbolAddress((void**)&porth, g_part_orth);
    cudaGetSymbolAddress((void**)&plc, g_part_lc);

    cudaFuncSetAttribute(hm_gemm_qkv, cudaFuncAttributeMaxDynamicSharedMemorySize, GEMM_SMEM);
    cudaFuncSetAttribute(hm_proj, cudaFuncAttributeMaxDynamicSharedMemorySize, GEMM_SMEM);
    cudaFuncSetAttribute(hm_ortho, cudaFuncAttributeMaxDynamicSharedMemorySize, ORTHO_SMEM);
    cudaFuncSetAttribute(attn_hmma, cudaFuncAttributeMaxDynamicSharedMemorySize, ATTN_SMEM);

    const int chunk = (out_size - 3) / 4;  // 2097152 = 4096*512

    // QKV projections -> bf16 hi/lo (both in one launch)
    QkvArgs qa;
    qa.A[0] = x; qa.B[0] = Wq1; qa.Oh[0] = q1h; qa.Ol[0] = q1l;
    qa.A[1] = y; qa.B[1] = Wq2; qa.Oh[1] = q2h; qa.Ol[1] = q2l;
    hm_gemm_qkv<<<dim3(16, 32, 2), 256, GEMM_SMEM>>>(qa);

    // Ortho losses
    hm_ortho<<<dim3(8, 8, 64), 256, ORTHO_SMEM>>>(q1h, q1l, q2h, q2l, porth);

    // 4 attentions (HMMA flash, cp.async double-buffered):
    AttnArgs aa;
    aa.qh[0] = q2h;        aa.ql[0] = q2l;
    aa.kh[0] = q1h + 512;  aa.kl[0] = q1l + 512;
    aa.vh[0] = q1h + 1024; aa.vl[0] = q1l + 1024; aa.o[0] = pre;
    aa.qh[1] = q1h;        aa.ql[1] = q1l;
    aa.kh[1] = q2h + 512;  aa.kl[1] = q2l + 512;
    aa.vh[1] = q2h + 1024; aa.vl[1] = q2l + 1024; aa.o[1] = pre + 2097152;
    aa.qh[2] = q1h + 1536; aa.ql[2] = q1l + 1536;
    aa.kh[2] = q1h + 512;  aa.kl[2] = q1l + 512;
    aa.vh[2] = q1h + 1024; aa.vl[2] = q1l + 1024; aa.o[2] = pre + 2 * 2097152;
    aa.qh[3] = q2h + 1536; aa.ql[3] = q2l + 1536;
    aa.kh[3] = q2h + 512;  aa.kl[3] = q2l + 512;
    aa.vh[3] = q2h + 1024; aa.vl[3] = q2l + 1024; aa.o[3] = pre + 3 * 2097152;
    attn_hmma<<<dim3(8, 32, 4), 256, ATTN_SMEM>>>(aa);

    // Output projections (batched) straight into d_out (xc, yc, xt, yt)
    ProjArgs pa;
    for (int i = 0; i < 4; i++) {
        pa.A[i] = pre + (size_t)i * 2097152;
        pa.B[i] = W[i];
        pa.bias[i] = bb[i];
        pa.C[i] = out + (size_t)i * chunk;
    }
    hm_proj<<<dim3(4, 32, 4), 256, GEMM_SMEM>>>(pa);

    // lc on post-projection xc, yc
    lc_kernel<<<4096, 128>>>(out, out + chunk, plc);

    // scalars: lorthx, lorthy, lc
    finalize_kernel<<<1, 256>>>(porth, plc, out + (size_t)out_size - 3);
}